// round 10
// baseline (speedup 1.0000x reference)
#include <cuda_runtime.h>
#include <math.h>
#include <float.h>

#define BB 16
#define SS 64
#define MM 2048
#define DD 256
#define TK 8
#define OV 512
#define NB 128
#define SCALE 0.0625f

// ---- persistent state (no runtime allocs) ----
__device__ float g_ovl[BB*OV*DD];
__device__ int   g_slot[BB*MM];
__device__ int   g_ovcnt[BB];
__device__ float g_qk[SS*BB*DD];      // [t][b][d]
__device__ float g_gx[SS*BB*DD];      // [t][b][d]
__device__ float g_AT[DD*DD];         // [j][d]
__device__ float g_avec[DD];
__device__ float g_WuT1[DD*DD];       // [j][d]
__device__ float g_W2[DD*DD];         // [d][j]
__device__ float g_cvec[DD];
__device__ float g_psum[NB*BB];       // [k][b]
__device__ float g_part[NB*DD*BB];    // [k][d][b]
__device__ float g_h[DD*BB];          // [j][b] unnormalized
__device__ float g_zinv[BB];
__device__ float g_cv[NB*BB*TK];      // per-chunk top-8 candidate values
__device__ int   g_ci[NB*BB*TK];      // per-chunk top-8 candidate indices
__device__ int   g_tk[BB*TK*3];
// tree-barrier state: monotonic across launches (zero-init at module load)
__device__ int   g_cnt[8*32];         // per-group counters, 128B stride
__device__ int   g_rcnt;
__device__ int   g_genA[8*32];        // generation copies, 128B stride

// =================== tree grid barrier ===================
__device__ __forceinline__ void gbar(int T, int grp){
  __syncthreads();
  if (threadIdx.x == 0){
    int old;
    asm volatile("atom.acq_rel.gpu.global.add.s32 %0, [%1], %2;"
                 : "=r"(old) : "l"(&g_cnt[grp*32]), "r"(1) : "memory");
    if (old == T*16 - 1){
      int r;
      asm volatile("atom.acq_rel.gpu.global.add.s32 %0, [%1], %2;"
                   : "=r"(r) : "l"(&g_rcnt), "r"(1) : "memory");
      if (r == T*8 - 1){
        #pragma unroll
        for (int g=0; g<8; g++)
          asm volatile("st.release.gpu.global.s32 [%0], %1;"
                       :: "l"(&g_genA[g*32]), "r"(T) : "memory");
      }
    }
    int gv;
    do {
      asm volatile("ld.acquire.gpu.global.s32 %0, [%1];"
                   : "=r"(gv) : "l"(&g_genA[grp*32]) : "memory");
    } while (gv < T);
  }
  __syncthreads();
}

__device__ __forceinline__ float dot4acc(float4 a, float4 b, float acc){
  acc = fmaf(a.x, b.x, acc);
  acc = fmaf(a.y, b.y, acc);
  acc = fmaf(a.z, b.z, acc);
  acc = fmaf(a.w, b.w, acc);
  return acc;
}

// =================== the single kernel ===================
__global__ void __launch_bounds__(256, 1)
persist(const float* __restrict__ x, const float* __restrict__ memory,
        const float* __restrict__ Wq, const float* __restrict__ bq,
        const float* __restrict__ Wk, const float* __restrict__ Wv,
        const float* __restrict__ bv, const float* __restrict__ Wu,
        const float* __restrict__ bu, float* __restrict__ out){
  extern __shared__ float dsm[];
  float* rowsf = dsm;          // [16][256] base rows (persistent after init)
  float* qks   = dsm + 4096;   // [16][256] qk[b][j] for current t
  float* sbuf  = dsm + 8192;   // AB: spart[d][b] ; C2: h[j][b]

  __shared__ float sc[16][17];
  __shared__ __align__(16) float esm[16][16];
  __shared__ int   dlist[256];
  __shared__ int   dcnt_s;
  __shared__ float warrv[8]; __shared__ int warri[8];
  __shared__ int   idxs_s[TK];
  __shared__ int   chosen_s;
  __shared__ __align__(16) float4 sred4[256];
  __shared__ float zred[4];
  __shared__ __align__(16) float wrow[4*DD];
  __shared__ float cacc[16][4][9];
  __shared__ float sgate[16][2];
  __shared__ int   tk_s[BB*TK*3];
  __shared__ float zin_s[16];
  __shared__ float sbv[2], scv[2];

  int blk = blockIdx.x, tid = threadIdx.x;
  int grp = blk>>4;
  int m0 = blk*16;
  int wid = tid>>5, lane = tid&31;
  int dd0 = blk*2;

  // barrier generation base (stable value from previous launch / zero)
  int T0 = __ldcg(&g_genA[0]);

  // ================= init stage 1 =================
  if (blk < 32){                       // WuT1[j][d] = Wu[d][j]
    int base = blk*2048;
    #pragma unroll
    for (int z=0;z<8;z++){ int e = base + z*256 + tid; int d = e>>8, j = e&255;
      g_WuT1[j*DD+d] = Wu[(size_t)d*2*DD + j]; }
  } else if (blk < 48){                // A tiles: g_AT[j][d]
    float (*aq)[68] = (float(*)[68])dsm;
    float (*ak)[68] = (float(*)[68])(dsm + 16*68);
    int tn = blk-32, j0 = (tn>>2)*64, d0 = (tn&3)*64;
    int ty = tid>>4, tx = tid&15;
    float acc[16];
    #pragma unroll
    for (int z=0;z<16;z++) acc[z]=0.f;
    for (int ib=0; ib<DD; ib+=16){
      #pragma unroll
      for (int z=0;z<4;z++){ int e = z*256+tid; int i=e>>6, j=e&63;
        aq[i][j] = Wq[(size_t)(ib+i)*DD + j0 + j];
        ak[i][j] = Wk[(size_t)(ib+i)*DD + d0 + j]; }
      __syncthreads();
      #pragma unroll
      for (int i=0;i<16;i++){
        float qv[4], kv[4];
        #pragma unroll
        for (int u=0;u<4;u++){ qv[u]=aq[i][ty*4+u]; kv[u]=ak[i][tx*4+u]; }
        #pragma unroll
        for (int jr=0;jr<4;jr++)
          #pragma unroll
          for (int dr=0;dr<4;dr++) acc[jr*4+dr] = fmaf(qv[jr], kv[dr], acc[jr*4+dr]);
      }
      __syncthreads();
    }
    #pragma unroll
    for (int jr=0;jr<4;jr++)
      #pragma unroll
      for (int dr=0;dr<4;dr++)
        g_AT[(size_t)(j0+ty*4+jr)*DD + d0+tx*4+dr] = acc[jr*4+dr]*SCALE;
  } else if (blk < 64){                // W2 tiles [d][i]
    float (*wv)[68] = (float(*)[68])dsm;
    float (*wu)[68] = (float(*)[68])(dsm + 16*68);
    int tn = blk-48, i0 = (tn>>2)*64, d0 = (tn&3)*64;
    int ty = tid>>4, tx = tid&15;
    float acc[16];
    #pragma unroll
    for (int z=0;z<16;z++) acc[z]=0.f;
    for (int jb=0; jb<DD; jb+=16){
      #pragma unroll
      for (int z=0;z<4;z++){ int e = z*256+tid; int jj=e>>6, ii=e&63;
        wv[jj][ii] = Wv[(size_t)(jb+jj)*DD + i0 + ii];
        wu[jj][ii] = Wu[(size_t)(d0+ii)*2*DD + DD + jb + jj]; }
      __syncthreads();
      #pragma unroll
      for (int jj=0;jj<16;jj++){
        float vv[4], uv[4];
        #pragma unroll
        for (int u=0;u<4;u++){ vv[u]=wv[jj][ty*4+u]; uv[u]=wu[jj][tx*4+u]; }
        #pragma unroll
        for (int ir=0;ir<4;ir++)
          #pragma unroll
          for (int dr=0;dr<4;dr++) acc[ir*4+dr] = fmaf(vv[ir], uv[dr], acc[ir*4+dr]);
      }
      __syncthreads();
    }
    #pragma unroll
    for (int ir=0;ir<4;ir++)
      #pragma unroll
      for (int dr=0;dr<4;dr++)
        g_W2[(size_t)(d0+tx*4+dr)*DD + i0+ty*4+ir] = acc[ir*4+dr];
  } else if (blk < 80){                // slot map clear
    int base = (blk-64)*2048;
    #pragma unroll
    for (int z=0;z<8;z++) g_slot[base + z*256 + tid] = -1;
  } else if (blk == 80){
    if (tid < BB) g_ovcnt[tid] = 0;
  } else if (blk == 81){               // avec
    __shared__ float bqs[DD];
    bqs[tid] = bq[tid]; __syncthreads();
    float acc = 0.f;
    #pragma unroll 4
    for (int i=0;i<DD;i++) acc = fmaf(Wk[(size_t)i*DD+tid], bqs[i], acc);
    g_avec[tid] = acc*SCALE;
  } else if (blk == 82){               // cvec
    __shared__ float bvs[DD];
    bvs[tid] = bv[tid]; __syncthreads();
    float acc = 0.f;
    #pragma unroll 4
    for (int j=0;j<DD;j++) acc = fmaf(Wu[(size_t)tid*2*DD + DD + j], bvs[j], acc);
    g_cvec[tid] = acc;
  }
  gbar(T0+1, grp);

  // ================= init stage 2: qk / gx GEMMs =================
  {
    float (*xt)[17] = (float(*)[17])dsm;
    float (*wt)[68] = (float(*)[68])(dsm + 64*17);
    int which = blk>>6;
    int r = blk&63;
    int s0 = (r>>2)*64, d0 = (r&3)*64;
    const float* W = which ? g_WuT1 : g_AT;
    int ty = tid>>4, tx = tid&15;
    float acc[16];
    #pragma unroll
    for (int z=0;z<16;z++) acc[z]=0.f;
    for (int jb=0; jb<DD; jb+=16){
      { int ss = tid>>2, jq = tid&3;
        float4 xv = *(const float4*)&x[(size_t)(s0+ss)*DD + jb + jq*4];
        xt[ss][jq*4+0]=xv.x; xt[ss][jq*4+1]=xv.y; xt[ss][jq*4+2]=xv.z; xt[ss][jq*4+3]=xv.w; }
      #pragma unroll
      for (int z=0;z<4;z++){ int e = z*256+tid; int jj=e>>6, dd=e&63;
        wt[jj][dd] = W[(size_t)(jb+jj)*DD + d0 + dd]; }
      __syncthreads();
      #pragma unroll
      for (int jj=0;jj<16;jj++){
        float xv[4], wv4[4];
        #pragma unroll
        for (int u=0;u<4;u++){ xv[u]=xt[ty*4+u][jj]; wv4[u]=wt[jj][tx*4+u]; }
        #pragma unroll
        for (int sr=0;sr<4;sr++)
          #pragma unroll
          for (int dr=0;dr<4;dr++) acc[sr*4+dr] = fmaf(xv[sr], wv4[dr], acc[sr*4+dr]);
      }
      __syncthreads();
    }
    float* dst = which ? g_gx : g_qk;
    const float* bias = which ? bu : g_avec;
    #pragma unroll
    for (int sr=0;sr<4;sr++){
      int s = s0 + ty*4 + sr;
      int b = s>>6, t = s&63;
      size_t ro = (size_t)(t*BB+b)*DD + d0 + tx*4;
      #pragma unroll
      for (int dr=0;dr<4;dr++) dst[ro+dr] = acc[sr*4+dr] + bias[d0+tx*4+dr];
    }
  }
  gbar(T0+2, grp);

  // ================= persistent smem loads =================
  for (int i=tid;i<16*DD;i+=256) rowsf[i] = memory[(size_t)m0*DD + i];
  for (int i=tid;i<16*DD;i+=256) qks[i]   = g_qk[i];
  for (int i=tid;i<2*DD;i+=256){ wrow[i] = Wv[(size_t)dd0*DD + i]; wrow[2*DD+i] = g_W2[(size_t)dd0*DD + i]; }
  if (tid<2){ sbv[tid] = bv[dd0+tid]; scv[tid] = g_cvec[dd0+tid]; }

  int bid = T0+2;
  for (int t=0;t<SS;t++){
    // ================= Phase AB =================
    if (tid==0) dcnt_s = 0;
    __syncthreads();
    {
      int b = tid>>4, r = tid&15;
      int s = __ldcg(&g_slot[b*MM + m0 + r]);
      if (s >= 0){ int p = atomicAdd(&dcnt_s,1); dlist[p] = (b<<16)|(r<<12)|s; }
    }
    {
      int jq = tid&15, bq0 = ((tid>>4)&3)*4, r0 = (tid>>6)*4;
      float acc[16];
      #pragma unroll
      for (int zz=0;zz<16;zz++) acc[zz]=0.f;
      #pragma unroll
      for (int jj=0;jj<4;jj++){
        int jb = jj*64 + jq*4;
        float4 qa[4], ra[4];
        #pragma unroll
        for (int u=0;u<4;u++){
          qa[u] = *(const float4*)&qks[(bq0+u)*256 + jb];
          ra[u] = *(const float4*)&rowsf[(r0+u)*256 + jb];
        }
        #pragma unroll
        for (int bi=0;bi<4;bi++)
          #pragma unroll
          for (int ri=0;ri<4;ri++)
            acc[bi*4+ri] = dot4acc(qa[bi], ra[ri], acc[bi*4+ri]);
      }
      #pragma unroll
      for (int off=8; off; off>>=1){
        #pragma unroll
        for (int zz=0;zz<16;zz++) acc[zz] += __shfl_xor_sync(0xffffffffu, acc[zz], off);
      }
      if (jq==0){
        #pragma unroll
        for (int bi=0;bi<4;bi++)
          #pragma unroll
          for (int ri=0;ri<4;ri++) sc[bq0+bi][r0+ri] = acc[bi*4+ri];
      }
    }
    __syncthreads();
    int dn = dcnt_s;
    for (int e=wid; e<dn; e+=8){
      int pk = dlist[e]; int eb = pk>>16, er = (pk>>12)&15, es = pk&0xfff;
      const float* ov = g_ovl + ((size_t)eb*OV + es)*DD;
      float a2 = 0.f;
      #pragma unroll
      for (int k=0;k<8;k++) a2 = fmaf(__ldcg(&ov[lane+32*k]), qks[eb*256 + lane+32*k], a2);
      #pragma unroll
      for (int off=16; off; off>>=1) a2 += __shfl_xor_sync(0xffffffffu, a2, off);
      if (lane==0) sc[eb][er] = a2;
    }
    __syncthreads();
    {
      int b = tid>>4, r = tid&15;
      float e = expf(sc[b][r]);
      esm[r][b] = e;
      float ps = e;
      #pragma unroll
      for (int off=8; off; off>>=1) ps += __shfl_xor_sync(0xffffffffu, ps, off);
      if (r==0) __stcg(&g_psum[blk*16 + b], ps);
    }
    __syncthreads();
    // per-chunk top-8 candidates (half-warp per batch)
    if (t < SS-1){
      int hw = lane>>4, hl = lane&15;
      int b = wid*2 + hw;
      float v = sc[b][hl];
      int ix = m0 + hl;
      #pragma unroll
      for (int round=0; round<TK; round++){
        float bv2 = v; int bix = ix;
        #pragma unroll
        for (int off=8; off; off>>=1){
          float ovv = __shfl_xor_sync(0xffffffffu, bv2, off);
          int   oi  = __shfl_xor_sync(0xffffffffu, bix, off);
          if (ovv > bv2 || (ovv==bv2 && oi<bix)){ bv2=ovv; bix=oi; }
        }
        if (hl==0){
          __stcg(&g_cv[(blk*BB+b)*TK + round], bv2);
          __stcg(&g_ci[(blk*BB+b)*TK + round], bix);
        }
        if (ix == bix) v = -FLT_MAX;
      }
    }
    // partials: thread owns d=tid
    {
      float acc[16];
      #pragma unroll
      for (int z=0;z<16;z++) acc[z]=0.f;
      #pragma unroll
      for (int r=0;r<16;r++){
        float rv = rowsf[r*256 + tid];
        float4 e0 = *(const float4*)&esm[r][0];
        float4 e1 = *(const float4*)&esm[r][4];
        float4 e2 = *(const float4*)&esm[r][8];
        float4 e3 = *(const float4*)&esm[r][12];
        acc[0]=fmaf(e0.x,rv,acc[0]);  acc[1]=fmaf(e0.y,rv,acc[1]);
        acc[2]=fmaf(e0.z,rv,acc[2]);  acc[3]=fmaf(e0.w,rv,acc[3]);
        acc[4]=fmaf(e1.x,rv,acc[4]);  acc[5]=fmaf(e1.y,rv,acc[5]);
        acc[6]=fmaf(e1.z,rv,acc[6]);  acc[7]=fmaf(e1.w,rv,acc[7]);
        acc[8]=fmaf(e2.x,rv,acc[8]);  acc[9]=fmaf(e2.y,rv,acc[9]);
        acc[10]=fmaf(e2.z,rv,acc[10]);acc[11]=fmaf(e2.w,rv,acc[11]);
        acc[12]=fmaf(e3.x,rv,acc[12]);acc[13]=fmaf(e3.y,rv,acc[13]);
        acc[14]=fmaf(e3.z,rv,acc[14]);acc[15]=fmaf(e3.w,rv,acc[15]);
      }
      #pragma unroll
      for (int z=0;z<16;z++) sbuf[tid*16 + z] = acc[z];
      for (int e2=0;e2<dn;e2++){
        int pk = dlist[e2]; int eb = pk>>16, er = (pk>>12)&15, es = pk&0xfff;
        float ev = esm[er][eb];
        float ovv = __ldcg(&g_ovl[((size_t)eb*OV + es)*DD + tid]);
        sbuf[tid*16 + eb] += ev*(ovv - rowsf[er*256 + tid]);
      }
      float4* gp4 = (float4*)g_part;
      const float4* sp4 = (const float4*)&sbuf[tid*16];
      #pragma unroll
      for (int z=0;z<4;z++) __stcg(&gp4[((size_t)blk*256 + tid)*4 + z], sp4[z]);
    }
    gbar(++bid, grp);

    // ================= Phase C1 =================
    {
      const float4* gp4 = (const float4*)g_part;
      int q = tid&7, k0 = tid>>3;
      float4 a4 = make_float4(0.f,0.f,0.f,0.f);
      #pragma unroll
      for (int p=0;p<4;p++){
        float4 v = __ldcg(&gp4[(size_t)(k0 + p*32)*1024 + dd0*4 + q]);
        a4.x += v.x; a4.y += v.y; a4.z += v.z; a4.w += v.w;
      }
      sred4[tid] = a4;
      __syncthreads();
      #pragma unroll
      for (int off=128; off>=8; off>>=1){
        if (tid < off){
          float4 o = sred4[tid+off]; float4 m = sred4[tid];
          m.x+=o.x; m.y+=o.y; m.z+=o.z; m.w+=o.w;
          sred4[tid] = m;
        }
        __syncthreads();
      }
      if (tid < 8) __stcg(&((float4*)g_h)[dd0*4 + tid], sred4[tid]);
    }
    if (t+1 < SS){
      const float* qsrc = g_qk + (size_t)(t+1)*BB*DD;
      for (int i=tid;i<16*DD;i+=256) qks[i] = qsrc[i];
    }
    if (blk < BB){
      int b2 = blk;
      float zp = (tid < NB) ? __ldcg(&g_psum[tid*16 + b2]) : 0.f;
      #pragma unroll
      for (int off=16; off; off>>=1) zp += __shfl_xor_sync(0xffffffffu, zp, off);
      if (lane==0 && wid<4) zred[wid] = zp;
      __syncthreads();
      if (tid==0) __stcg(&g_zinv[b2], 1.0f/(zred[0]+zred[1]+zred[2]+zred[3]));
      if (t < SS-1){
        // merge 128x8 candidates
        int kk = tid>>1, q0 = (tid&1)*4;
        float4 cv4 = __ldcg((const float4*)&g_cv[(size_t)(kk*BB + b2)*TK + q0]);
        int4   ci4 = __ldcg((const int4*)  &g_ci[(size_t)(kk*BB + b2)*TK + q0]);
        float v[4] = {cv4.x,cv4.y,cv4.z,cv4.w};
        int  ix[4] = {ci4.x,ci4.y,ci4.z,ci4.w};
        for (int round=0; round<TK; round++){
          float bv2 = v[0]; int bix = ix[0];
          #pragma unroll
          for (int z=1;z<4;z++){
            if (v[z] > bv2 || (v[z]==bv2 && ix[z]<bix)){ bv2=v[z]; bix=ix[z]; }
          }
          #pragma unroll
          for (int off=16; off; off>>=1){
            float ovv = __shfl_xor_sync(0xffffffffu, bv2, off);
            int   oi  = __shfl_xor_sync(0xffffffffu, bix, off);
            if (ovv > bv2 || (ovv==bv2 && oi<bix)){ bv2=ovv; bix=oi; }
          }
          if (lane==0){ warrv[wid]=bv2; warri[wid]=bix; }
          __syncthreads();
          if (tid==0){
            float bb = warrv[0]; int bj = warri[0];
            for (int w=1;w<8;w++){
              if (warrv[w]>bb || (warrv[w]==bb && warri[w]<bj)){ bb=warrv[w]; bj=warri[w]; }
            }
            idxs_s[round] = bj; chosen_s = bj;
          }
          __syncthreads();
          int ch = chosen_s;
          #pragma unroll
          for (int z=0;z<4;z++) if (ix[z]==ch) v[z] = -FLT_MAX;
        }
        if (tid==0){
          int cnt = __ldcg(&g_ovcnt[b2]);
          for (int i=0;i<TK;i++){
            int row = idxs_s[i];
            int s = __ldcg(&g_slot[b2*MM+row]);
            int prev = s;
            if (s < 0){ s = cnt++; __stcg(&g_slot[b2*MM+row], s); }
            __stcg(&g_tk[b2*24 + i*3 + 0], row);
            __stcg(&g_tk[b2*24 + i*3 + 1], prev);
            __stcg(&g_tk[b2*24 + i*3 + 2], s);
          }
          __stcg(&g_ovcnt[b2], cnt);
        }
      }
    }
    gbar(++bid, grp);

    // ================= Phase C2 =================
    {
      const float4* h4g = (const float4*)g_h;
      float4* s4 = (float4*)sbuf;
      for (int i=tid;i<1024;i+=256) s4[i] = __ldcg(&h4g[i]);
      if (tid < 16) zin_s[tid] = __ldcg(&g_zinv[tid]);
      if (t < SS-1){
        for (int i=tid;i<BB*TK*3;i+=256) tk_s[i] = __ldcg(&g_tk[i]);
      }
      __syncthreads();
      {
        int b = tid&15, jseg = tid>>4;
        float a0=0.f, a1=0.f, a2=0.f, a3=0.f;
        #pragma unroll
        for (int jj=0;jj<16;jj++){
          int j = jseg*16 + jj;
          float hv = sbuf[j*16 + b];
          a0 = fmaf(wrow[j],        hv, a0);
          a1 = fmaf(wrow[256 + j],  hv, a1);
          a2 = fmaf(wrow[512 + j],  hv, a2);
          a3 = fmaf(wrow[768 + j],  hv, a3);
        }
        a0 += __shfl_xor_sync(0xffffffffu, a0, 16);
        a1 += __shfl_xor_sync(0xffffffffu, a1, 16);
        a2 += __shfl_xor_sync(0xffffffffu, a2, 16);
        a3 += __shfl_xor_sync(0xffffffffu, a3, 16);
        if ((tid&16)==0){
          cacc[b][0][wid]=a0; cacc[b][1][wid]=a1; cacc[b][2][wid]=a2; cacc[b][3][wid]=a3;
        }
      }
      __syncthreads();
      if (tid < 64){
        int b = tid&15, o = tid>>4;
        float s = 0.f;
        #pragma unroll
        for (int w=0;w<8;w++) s += cacc[b][o][w];
        float zi = zin_s[b];
        if (o < 2){
          out[((size_t)b*SS+t)*DD + dd0 + o] = s*zi + sbv[o];
        } else {
          int di = o-2;
          float gg = s*zi + scv[di] + __ldg(&g_gx[((size_t)t*BB+b)*DD + dd0 + di]);
          sgate[b][di] = 1.0f/(1.0f+expf(-gg));
        }
      }
      __syncthreads();
      if (t < SS-1){
        int ent = tid>>1, di = tid&1;
        int b = ent>>3, i = ent&7;
        int row  = tk_s[(b*TK+i)*3 + 0];
        int prev = tk_s[(b*TK+i)*3 + 1];
        int slot = tk_s[(b*TK+i)*3 + 2];
        int d = dd0 + di;
        float old = (prev < 0) ? __ldg(&memory[(size_t)row*DD + d])
                               : __ldcg(&g_ovl[((size_t)b*OV + prev)*DD + d]);
        float g = sgate[b][di];
        float xd = __ldg(&x[((size_t)b*SS+t)*DD + d]);
        __stcg(&g_ovl[((size_t)b*OV + slot)*DD + d], old + g*(xd - old));
      }
    }
    gbar(++bid, grp);
  }
}

// =================== launch: single kernel ===================
extern "C" void kernel_launch(void* const* d_in, const int* in_sizes, int n_in,
                              void* d_out, int out_size){
  const float* x      = (const float*)d_in[0];
  const float* memory = (const float*)d_in[1];
  const float* Wq     = (const float*)d_in[2];
  const float* bq     = (const float*)d_in[3];
  const float* Wk     = (const float*)d_in[4];
  // bk contributes only a softmax-invariant constant -> dropped
  const float* Wv     = (const float*)d_in[6];
  const float* bv     = (const float*)d_in[7];
  const float* Wu     = (const float*)d_in[8];
  const float* bu     = (const float*)d_in[9];
  float* out = (float*)d_out;

  static int attr_done = 0;
  if (!attr_done){
    cudaFuncSetAttribute(persist, cudaFuncAttributeMaxDynamicSharedMemorySize, 49152);
    attr_done = 1;
  }

  persist<<<NB, 256, 49152>>>(x, memory, Wq, bq, Wk, Wv, bv, Wu, bu, out);
}

// round 11
// speedup vs baseline: 1.2381x; 1.2381x over previous
#include <cuda_runtime.h>
#include <math.h>
#include <float.h>

#define BB 16
#define SS 64
#define MM 2048
#define DD 256
#define TK 8
#define OV 512
#define NB 128
#define NT 512
#define SCALE 0.0625f

// ---- persistent state (no runtime allocs) ----
__device__ float g_ovl[BB*OV*DD];
__device__ int   g_slot[BB*MM];
__device__ int   g_ovcnt[BB];
__device__ float g_qk[SS*BB*DD];      // [t][b][d]
__device__ float g_gx[SS*BB*DD];      // [t][b][d]
__device__ float g_AT[DD*DD];         // [j][d]
__device__ float g_avec[DD];
__device__ float g_WuT1[DD*DD];       // [j][d]
__device__ float g_W2[DD*DD];         // [d][j]
__device__ float g_cvec[DD];
__device__ float g_scores[BB*MM];     // [b][m]
__device__ float g_psum[NB*BB];       // [k][b]
__device__ float g_part[NB*DD*BB];    // [k][d][b]
__device__ float g_h[DD*BB];          // [j][b] unnormalized
__device__ float g_zinv[BB];
__device__ int   g_tk[BB*TK*3];
__device__ int   g_count;
__device__ int   g_gen2;

// =================== init launch 1 ===================
__global__ void p_init1(const float* __restrict__ Wq, const float* __restrict__ bq,
                        const float* __restrict__ Wk, const float* __restrict__ Wv,
                        const float* __restrict__ bv, const float* __restrict__ Wu){
  int blk = blockIdx.x, tid = threadIdx.x;
  if (blk < 32){                       // WuT1[j][d] = Wu[d][j]
    int base = blk*2048;
    #pragma unroll
    for (int z=0;z<8;z++){ int e = base + z*256 + tid; int d = e>>8, j = e&255;
      g_WuT1[j*DD+d] = Wu[(size_t)d*2*DD + j]; }
  } else if (blk < 48){                // A tiles: g_AT[j][d]
    __shared__ float aq[16][68], ak[16][68];
    int tn = blk-32, j0 = (tn>>2)*64, d0 = (tn&3)*64;
    int ty = tid>>4, tx = tid&15;
    float acc[16];
    #pragma unroll
    for (int z=0;z<16;z++) acc[z]=0.f;
    for (int ib=0; ib<DD; ib+=16){
      #pragma unroll
      for (int z=0;z<4;z++){ int e = z*256+tid; int i=e>>6, j=e&63;
        aq[i][j] = Wq[(size_t)(ib+i)*DD + j0 + j];
        ak[i][j] = Wk[(size_t)(ib+i)*DD + d0 + j]; }
      __syncthreads();
      #pragma unroll
      for (int i=0;i<16;i++){
        float qv[4], kv[4];
        #pragma unroll
        for (int u=0;u<4;u++){ qv[u]=aq[i][ty*4+u]; kv[u]=ak[i][tx*4+u]; }
        #pragma unroll
        for (int jr=0;jr<4;jr++)
          #pragma unroll
          for (int dr=0;dr<4;dr++) acc[jr*4+dr] = fmaf(qv[jr], kv[dr], acc[jr*4+dr]);
      }
      __syncthreads();
    }
    #pragma unroll
    for (int jr=0;jr<4;jr++)
      #pragma unroll
      for (int dr=0;dr<4;dr++)
        g_AT[(size_t)(j0+ty*4+jr)*DD + d0+tx*4+dr] = acc[jr*4+dr]*SCALE;
  } else if (blk < 64){                // W2 tiles [d][i]
    __shared__ float wv[16][68], wu[16][68];
    int tn = blk-48, i0 = (tn>>2)*64, d0 = (tn&3)*64;
    int ty = tid>>4, tx = tid&15;
    float acc[16];
    #pragma unroll
    for (int z=0;z<16;z++) acc[z]=0.f;
    for (int jb=0; jb<DD; jb+=16){
      #pragma unroll
      for (int z=0;z<4;z++){ int e = z*256+tid; int jj=e>>6, ii=e&63;
        wv[jj][ii] = Wv[(size_t)(jb+jj)*DD + i0 + ii];
        wu[jj][ii] = Wu[(size_t)(d0+ii)*2*DD + DD + jb + jj]; }
      __syncthreads();
      #pragma unroll
      for (int jj=0;jj<16;jj++){
        float vv[4], uv[4];
        #pragma unroll
        for (int u=0;u<4;u++){ vv[u]=wv[jj][ty*4+u]; uv[u]=wu[jj][tx*4+u]; }
        #pragma unroll
        for (int ir=0;ir<4;ir++)
          #pragma unroll
          for (int dr=0;dr<4;dr++) acc[ir*4+dr] = fmaf(vv[ir], uv[dr], acc[ir*4+dr]);
      }
      __syncthreads();
    }
    #pragma unroll
    for (int ir=0;ir<4;ir++)
      #pragma unroll
      for (int dr=0;dr<4;dr++)
        g_W2[(size_t)(d0+tx*4+dr)*DD + i0+ty*4+ir] = acc[ir*4+dr];
  } else if (blk < 80){                // slot map clear
    int base = (blk-64)*2048;
    #pragma unroll
    for (int z=0;z<8;z++) g_slot[base + z*256 + tid] = -1;
  } else if (blk == 80){
    if (tid==0){ g_count = 0; g_gen2 = 0; }
    if (tid < BB) g_ovcnt[tid] = 0;
  } else if (blk == 81){               // avec
    __shared__ float bqs[DD];
    bqs[tid] = bq[tid]; __syncthreads();
    float acc = 0.f;
    #pragma unroll 4
    for (int i=0;i<DD;i++) acc = fmaf(Wk[(size_t)i*DD+tid], bqs[i], acc);
    g_avec[tid] = acc*SCALE;
  } else if (blk == 82){               // cvec
    __shared__ float bvs[DD];
    bvs[tid] = bv[tid]; __syncthreads();
    float acc = 0.f;
    #pragma unroll 4
    for (int j=0;j<DD;j++) acc = fmaf(Wu[(size_t)tid*2*DD + DD + j], bvs[j], acc);
    g_cvec[tid] = acc;
  }
}

// =================== init launch 2: qk / gx GEMMs ===================
__global__ void p_init2(const float* __restrict__ x, const float* __restrict__ bu){
  __shared__ float xt[64][17];
  __shared__ float wt[16][68];
  int blk = blockIdx.x, tid = threadIdx.x;
  int which = blk>>6;
  int r = blk&63;
  int s0 = (r>>2)*64, d0 = (r&3)*64;
  const float* W = which ? g_WuT1 : g_AT;
  int ty = tid>>4, tx = tid&15;
  float acc[16];
  #pragma unroll
  for (int z=0;z<16;z++) acc[z]=0.f;
  for (int jb=0; jb<DD; jb+=16){
    { int ss = tid>>2, jq = tid&3;
      float4 xv = *(const float4*)&x[(size_t)(s0+ss)*DD + jb + jq*4];
      xt[ss][jq*4+0]=xv.x; xt[ss][jq*4+1]=xv.y; xt[ss][jq*4+2]=xv.z; xt[ss][jq*4+3]=xv.w; }
    #pragma unroll
    for (int z=0;z<4;z++){ int e = z*256+tid; int jj=e>>6, dd=e&63;
      wt[jj][dd] = W[(size_t)(jb+jj)*DD + d0 + dd]; }
    __syncthreads();
    #pragma unroll
    for (int jj=0;jj<16;jj++){
      float xv[4], wv4[4];
      #pragma unroll
      for (int u=0;u<4;u++){ xv[u]=xt[ty*4+u][jj]; wv4[u]=wt[jj][tx*4+u]; }
      #pragma unroll
      for (int sr=0;sr<4;sr++)
        #pragma unroll
        for (int dr=0;dr<4;dr++) acc[sr*4+dr] = fmaf(xv[sr], wv4[dr], acc[sr*4+dr]);
    }
    __syncthreads();
  }
  float* dst = which ? g_gx : g_qk;
  const float* bias = which ? bu : g_avec;
  #pragma unroll
  for (int sr=0;sr<4;sr++){
    int s = s0 + ty*4 + sr;
    int b = s>>6, t = s&63;
    size_t ro = (size_t)(t*BB+b)*DD + d0 + tx*4;
    #pragma unroll
    for (int dr=0;dr<4;dr++) dst[ro+dr] = acc[sr*4+dr] + bias[d0+tx*4+dr];
  }
}

// =================== flat grid barrier (proven in R8) ===================
__device__ __forceinline__ void gbar(int target){
  __syncthreads();
  if (threadIdx.x == 0){
    int old;
    asm volatile("atom.acq_rel.gpu.global.add.s32 %0, [%1], %2;"
                 : "=r"(old) : "l"(&g_count), "r"(1) : "memory");
    if (old == target*NB - 1){
      asm volatile("st.release.gpu.global.s32 [%0], %1;"
                   :: "l"(&g_gen2), "r"(target) : "memory");
    } else {
      int g;
      do {
        asm volatile("ld.acquire.gpu.global.s32 %0, [%1];"
                     : "=r"(g) : "l"(&g_gen2) : "memory");
      } while (g < target);
    }
  }
  __syncthreads();
}

__device__ __forceinline__ float dot4acc(float4 a, float4 b, float acc){
  acc = fmaf(a.x, b.x, acc);
  acc = fmaf(a.y, b.y, acc);
  acc = fmaf(a.z, b.z, acc);
  acc = fmaf(a.w, b.w, acc);
  return acc;
}

// =================== the persistent kernel (512 threads) ===================
__global__ void __launch_bounds__(NT, 1)
persist(const float* __restrict__ base, const float* __restrict__ x,
        const float* __restrict__ Wv, const float* __restrict__ bv,
        float* __restrict__ out){
  extern __shared__ float dsm[];
  float* rowsf = dsm;          // [16][256]
  float* qks   = dsm + 4096;   // [16][256]
  float* sbuf  = dsm + 8192;   // AB: spart[d][b] ; C2: h[j][b]

  __shared__ float sc[16][17];
  __shared__ __align__(16) float esm[16][16];   // [r][b]
  __shared__ int   dlist[256];
  __shared__ int   dcnt_s;
  __shared__ float warrv[8]; __shared__ int warri[8];
  __shared__ int   idxs_s[TK];
  __shared__ int   chosen_s;
  __shared__ __align__(16) float4 sred4[NT];
  __shared__ float zred[4];
  __shared__ __align__(16) float wrow[4*DD];
  __shared__ float cacc[16][4][9];
  __shared__ float sgate[16][2];
  __shared__ int   tk_s[BB*TK*3];
  __shared__ float zin_s[16];
  __shared__ float sbv[2], scv[2];

  int blk = blockIdx.x, tid = threadIdx.x;
  int m0 = blk*16;
  int wid = tid>>5, lane = tid&31;
  int dd0 = blk*2;

  // persistent smem loads
  for (int i=tid;i<16*DD;i+=NT) rowsf[i] = base[(size_t)m0*DD + i];
  for (int i=tid;i<16*DD;i+=NT) qks[i]   = g_qk[i];
  { int i = tid; if (i < 2*DD){ wrow[i] = Wv[(size_t)dd0*DD + i]; wrow[2*DD+i] = g_W2[(size_t)dd0*DD + i]; } }
  if (tid<2){ sbv[tid] = bv[dd0+tid]; scv[tid] = g_cvec[dd0+tid]; }

  int bid = 0;
  for (int t=0;t<SS;t++){
    // ================= Phase AB =================
    if (tid==0) dcnt_s = 0;
    __syncthreads();
    if (tid < 256){
      int b = tid>>4, r = tid&15;
      int s = __ldcg(&g_slot[b*MM + m0 + r]);
      if (s >= 0){ int p = atomicAdd(&dcnt_s,1); dlist[p] = (b<<16)|(r<<12)|s; }
    }
    // score GEMM: warp wid owns (bq0,r0) 4x4 tile; lane splits K 32 ways
    {
      int bq0 = (wid&3)*4, r0 = (wid>>2)*4;
      int j0 = lane*8;
      float acc[16];
      #pragma unroll
      for (int z=0;z<16;z++) acc[z]=0.f;
      #pragma unroll
      for (int hh=0; hh<2; hh++){
        int jb = j0 + hh*4;
        float4 qa[4], ra[4];
        #pragma unroll
        for (int u=0;u<4;u++){
          qa[u] = *(const float4*)&qks[(bq0+u)*256 + jb];
          ra[u] = *(const float4*)&rowsf[(r0+u)*256 + jb];
        }
        #pragma unroll
        for (int bi=0;bi<4;bi++)
          #pragma unroll
          for (int ri=0;ri<4;ri++)
            acc[bi*4+ri] = dot4acc(qa[bi], ra[ri], acc[bi*4+ri]);
      }
      #pragma unroll
      for (int off=16; off; off>>=1){
        #pragma unroll
        for (int z=0;z<16;z++) acc[z] += __shfl_xor_sync(0xffffffffu, acc[z], off);
      }
      if (lane==0){
        #pragma unroll
        for (int bi=0;bi<4;bi++)
          #pragma unroll
          for (int ri=0;ri<4;ri++) sc[bq0+bi][r0+ri] = acc[bi*4+ri];
      }
    }
    __syncthreads();
    int dn = dcnt_s;
    // dirty score fixes (16 warps)
    for (int e=wid; e<dn; e+=16){
      int pk = dlist[e]; int eb = pk>>16, er = (pk>>12)&15, es = pk&0xfff;
      const float* ov = g_ovl + ((size_t)eb*OV + es)*DD;
      float a2 = 0.f;
      #pragma unroll
      for (int k=0;k<8;k++) a2 = fmaf(__ldcg(&ov[lane+32*k]), qks[eb*256 + lane+32*k], a2);
      #pragma unroll
      for (int off=16; off; off>>=1) a2 += __shfl_xor_sync(0xffffffffu, a2, off);
      if (lane==0) sc[eb][er] = a2;
    }
    __syncthreads();
    if (tid < 256){
      int b = tid>>4, r = tid&15;
      float sv = sc[b][r];
      __stcg(&g_scores[b*MM + m0 + r], sv);
      float e = expf(sv);
      esm[r][b] = e;
      float ps = e;
      #pragma unroll
      for (int off=8; off; off>>=1) ps += __shfl_xor_sync(0xffffffffu, ps, off);
      if (r==0) __stcg(&g_psum[blk*16 + b], ps);
    }
    __syncthreads();
    // partials: 2 threads per d; half = tid&1 owns batches half*8..+7
    {
      int d = tid>>1, half = tid&1;
      float rv[16];
      #pragma unroll
      for (int r=0;r<16;r++) rv[r] = rowsf[r*256 + d];
      float4 A0 = make_float4(0.f,0.f,0.f,0.f), A1 = A0;
      #pragma unroll
      for (int r=0;r<16;r++){
        float4 e0 = *(const float4*)&esm[r][half*8];
        float4 e1 = *(const float4*)&esm[r][half*8+4];
        float rr = rv[r];
        A0.x = fmaf(e0.x, rr, A0.x); A0.y = fmaf(e0.y, rr, A0.y);
        A0.z = fmaf(e0.z, rr, A0.z); A0.w = fmaf(e0.w, rr, A0.w);
        A1.x = fmaf(e1.x, rr, A1.x); A1.y = fmaf(e1.y, rr, A1.y);
        A1.z = fmaf(e1.z, rr, A1.z); A1.w = fmaf(e1.w, rr, A1.w);
      }
      *(float4*)&sbuf[d*16 + half*8]     = A0;
      *(float4*)&sbuf[d*16 + half*8 + 4] = A1;
      // dirty corrections: only the half that owns eb acts
      #pragma unroll 4
      for (int e2=0; e2<dn; e2++){
        int pk = dlist[e2]; int eb = pk>>16;
        if ((eb>>3) == half){
          int er = (pk>>12)&15, es = pk&0xfff;
          float ev = esm[er][eb];
          float ovv = __ldcg(&g_ovl[((size_t)eb*OV + es)*DD + d]);
          sbuf[d*16 + eb] += ev*(ovv - rv[er]);
        }
      }
      float4* gp4 = (float4*)g_part;
      __stcg(&gp4[((size_t)blk*256 + d)*4 + half*2 + 0], *(const float4*)&sbuf[d*16 + half*8]);
      __stcg(&gp4[((size_t)blk*256 + d)*4 + half*2 + 1], *(const float4*)&sbuf[d*16 + half*8 + 4]);
    }
    gbar(++bid);

    // ================= Phase C1 =================
    {
      const float4* gp4 = (const float4*)g_part;
      int q = tid&7, kk = tid>>3;   // kk 0..63
      int dj = q>>2, q2 = q&3;
      float4 a4 = make_float4(0.f,0.f,0.f,0.f);
      #pragma unroll
      for (int p=0;p<2;p++){
        int k = kk + p*64;
        float4 v = __ldcg(&gp4[((size_t)k*256 + dd0 + dj)*4 + q2]);
        a4.x += v.x; a4.y += v.y; a4.z += v.z; a4.w += v.w;
      }
      sred4[tid] = a4;
      __syncthreads();
      #pragma unroll
      for (int off=256; off>=8; off>>=1){
        if (tid < off){
          float4 o = sred4[tid+off]; float4 m = sred4[tid];
          m.x+=o.x; m.y+=o.y; m.z+=o.z; m.w+=o.w;
          sred4[tid] = m;
        }
        __syncthreads();
      }
      if (tid < 8) __stcg(&((float4*)g_h)[dd0*4 + tid], sred4[tid]);
    }
    if (t+1 < SS){
      const float* qsrc = g_qk + (size_t)(t+1)*BB*DD;
      for (int i=tid;i<16*DD;i+=NT) qks[i] = qsrc[i];
    }
    if (blk < BB){
      int b2 = blk;
      float zp = (tid < NB) ? __ldcg(&g_psum[tid*16 + b2]) : 0.f;
      #pragma unroll
      for (int off=16; off; off>>=1) zp += __shfl_xor_sync(0xffffffffu, zp, off);
      if (lane==0 && wid<4) zred[wid] = zp;
      __syncthreads();
      if (tid==0) __stcg(&g_zinv[b2], 1.0f/(zred[0]+zred[1]+zred[2]+zred[3]));
      if (t < SS-1){
        // top-8 over 2048 scores; threads 0..255 hold 8 each
        float vloc[8];
        int base_m = (tid&255)*8;
        if (tid < 256){
          float4 va = __ldcg((const float4*)&g_scores[b2*MM + base_m]);
          float4 vb = __ldcg((const float4*)&g_scores[b2*MM + base_m + 4]);
          vloc[0]=va.x; vloc[1]=va.y; vloc[2]=va.z; vloc[3]=va.w;
          vloc[4]=vb.x; vloc[5]=vb.y; vloc[6]=vb.z; vloc[7]=vb.w;
        }
        for (int round=0; round<TK; round++){
          if (tid < 256){
            float v = -FLT_MAX; int bi2 = MM;
            #pragma unroll
            for (int k=0;k<8;k++){ if (vloc[k] > v){ v = vloc[k]; bi2 = base_m+k; } }
            #pragma unroll
            for (int off=16; off; off>>=1){
              float ov2 = __shfl_xor_sync(0xffffffffu, v, off);
              int   oi  = __shfl_xor_sync(0xffffffffu, bi2, off);
              if (ov2 > v || (ov2==v && oi<bi2)){ v=ov2; bi2=oi; }
            }
            if (lane==0){ warrv[wid]=v; warri[wid]=bi2; }
          }
          __syncthreads();
          if (tid==0){
            float bv2 = warrv[0]; int bj = warri[0];
            for (int w=1;w<8;w++){
              if (warrv[w]>bv2 || (warrv[w]==bv2 && warri[w]<bj)){ bv2=warrv[w]; bj=warri[w]; }
            }
            idxs_s[round] = bj; chosen_s = bj;
          }
          __syncthreads();
          if (tid < 256){
            int ch = chosen_s;
            if ((ch>>3) == tid) vloc[ch&7] = -FLT_MAX;
          }
        }
        // parallel slot assignment (warp 0)
        if (tid < 32){
          bool valid = lane < TK;
          int row = idxs_s[valid ? lane : 0];
          int s = valid ? __ldcg(&g_slot[b2*MM + row]) : 0;
          unsigned nm = __ballot_sync(0xffffffffu, valid && s < 0);
          int cnt0 = 0;
          if (lane==0) cnt0 = __ldcg(&g_ovcnt[b2]);
          cnt0 = __shfl_sync(0xffffffffu, cnt0, 0);
          if (valid){
            int prev = s, slot = s;
            if (s < 0){
              slot = cnt0 + __popc(nm & ((1u<<lane)-1));
              __stcg(&g_slot[b2*MM + row], slot);
            }
            __stcg(&g_tk[b2*24 + lane*3 + 0], row);
            __stcg(&g_tk[b2*24 + lane*3 + 1], prev);
            __stcg(&g_tk[b2*24 + lane*3 + 2], slot);
          }
          if (lane==0) __stcg(&g_ovcnt[b2], cnt0 + __popc(nm));
        }
      }
    }
    gbar(++bid);

    // ================= Phase C2 =================
    {
      const float4* h4g = (const float4*)g_h;
      float4* s4 = (float4*)sbuf;
      for (int i=tid;i<1024;i+=NT) s4[i] = __ldcg(&h4g[i]);
      if (tid < 16) zin_s[tid] = __ldcg(&g_zinv[tid]);
      if (t < SS-1){
        for (int i=tid;i<BB*TK*3;i+=NT) tk_s[i] = __ldcg(&g_tk[i]);
      }
      __syncthreads();
      if (tid < 256){
        int b = tid&15, jseg = tid>>4;
        float a0=0.f, a1=0.f, a2=0.f, a3=0.f;
        #pragma unroll
        for (int jj=0;jj<16;jj++){
          int j = jseg*16 + jj;
          float hv = sbuf[j*16 + b];
          a0 = fmaf(wrow[j],        hv, a0);
          a1 = fmaf(wrow[256 + j],  hv, a1);
          a2 = fmaf(wrow[512 + j],  hv, a2);
          a3 = fmaf(wrow[768 + j],  hv, a3);
        }
        a0 += __shfl_xor_sync(0xffffffffu, a0, 16);
        a1 += __shfl_xor_sync(0xffffffffu, a1, 16);
        a2 += __shfl_xor_sync(0xffffffffu, a2, 16);
        a3 += __shfl_xor_sync(0xffffffffu, a3, 16);
        if ((tid&16)==0){
          cacc[b][0][wid]=a0; cacc[b][1][wid]=a1; cacc[b][2][wid]=a2; cacc[b][3][wid]=a3;
        }
      }
      __syncthreads();
      if (tid < 64){
        int b = tid&15, o = tid>>4;
        float s = 0.f;
        #pragma unroll
        for (int w=0;w<8;w++) s += cacc[b][o][w];
        float zi = zin_s[b];
        if (o < 2){
          out[((size_t)b*SS+t)*DD + dd0 + o] = s*zi + sbv[o];
        } else {
          int di = o-2;
          float gg = s*zi + scv[di] + __ldg(&g_gx[((size_t)t*BB+b)*DD + dd0 + di]);
          sgate[b][di] = 1.0f/(1.0f+expf(-gg));
        }
      }
      __syncthreads();
      if (t < SS-1 && tid < 256){
        int ent = tid>>1, di = tid&1;
        int b = ent>>3, i = ent&7;
        int row  = tk_s[(b*TK+i)*3 + 0];
        int prev = tk_s[(b*TK+i)*3 + 1];
        int slot = tk_s[(b*TK+i)*3 + 2];
        int d = dd0 + di;
        float old = (prev < 0) ? __ldg(&base[(size_t)row*DD + d])
                               : __ldcg(&g_ovl[((size_t)b*OV + prev)*DD + d]);
        float g = sgate[b][di];
        float xd = __ldg(&x[((size_t)b*SS+t)*DD + d]);
        __stcg(&g_ovl[((size_t)b*OV + slot)*DD + d], old + g*(xd - old));
      }
    }
    gbar(++bid);
  }
}

// =================== launch ===================
extern "C" void kernel_launch(void* const* d_in, const int* in_sizes, int n_in,
                              void* d_out, int out_size){
  const float* x      = (const float*)d_in[0];
  const float* memory = (const float*)d_in[1];
  const float* Wq     = (const float*)d_in[2];
  const float* bq     = (const float*)d_in[3];
  const float* Wk     = (const float*)d_in[4];
  // bk contributes only a softmax-invariant constant -> dropped
  const float* Wv     = (const float*)d_in[6];
  const float* bv     = (const float*)d_in[7];
  const float* Wu     = (const float*)d_in[8];
  const float* bu     = (const float*)d_in[9];
  float* out = (float*)d_out;

  static int attr_done = 0;
  if (!attr_done){
    cudaFuncSetAttribute(persist, cudaFuncAttributeMaxDynamicSharedMemorySize, 49152);
    attr_done = 1;
  }

  p_init1<<<NB, 256>>>(Wq, bq, Wk, Wv, bv, Wu);
  p_init2<<<NB, 256>>>(x, bu);
  persist<<<NB, NT, 49152>>>(memory, x, Wv, bv, out);
}

// round 12
// speedup vs baseline: 1.4278x; 1.1533x over previous
#include <cuda_runtime.h>
#include <math.h>
#include <float.h>

#define BB 16
#define SS 64
#define MM 2048
#define DD 256
#define TK 8
#define OV 512
#define NB 128
#define NT 512
#define SCALE 0.0625f

// ---- persistent state (no runtime allocs) ----
__device__ float g_ovl[BB*OV*DD];
__device__ int   g_slot[BB*MM];
__device__ int   g_ovcnt[BB];
__device__ __align__(16) float g_qk[SS*BB*DD];
__device__ __align__(16) float g_gx[SS*BB*DD];
__device__ float g_AT[DD*DD];
__device__ float g_avec[DD];
__device__ float g_WuT1[DD*DD];
__device__ float g_W2[DD*DD];
__device__ float g_cvec[DD];
__device__ float g_psum[NB*BB];
__device__ __align__(16) float g_part[NB*DD*BB];   // [k][d][b]
__device__ __align__(16) float g_h[DD*BB];         // [j][b]
__device__ float g_zinv[BB];
__device__ __align__(16) float g_cv[NB*BB*TK];
__device__ __align__(16) int   g_ci[NB*BB*TK];
__device__ int   g_tk[BB*TK*3];
__device__ int   g_flag[NB*32];    // 128B-strided per-block arrival flags
__device__ int   g_gen2;

// =================== init launch 1 ===================
__global__ void p_init1(const float* __restrict__ Wq, const float* __restrict__ bq,
                        const float* __restrict__ Wk, const float* __restrict__ Wv,
                        const float* __restrict__ bv, const float* __restrict__ Wu){
  int blk = blockIdx.x, tid = threadIdx.x;
  if (blk < 32){
    int base = blk*2048;
    #pragma unroll
    for (int z=0;z<8;z++){ int e = base + z*256 + tid; int d = e>>8, j = e&255;
      g_WuT1[j*DD+d] = Wu[(size_t)d*2*DD + j]; }
  } else if (blk < 48){                // A tiles: g_AT[j][d]
    __shared__ float aq[16][68], ak[16][68];
    int tn = blk-32, j0 = (tn>>2)*64, d0 = (tn&3)*64;
    int ty = tid>>4, tx = tid&15;
    float acc[16];
    #pragma unroll
    for (int z=0;z<16;z++) acc[z]=0.f;
    for (int ib=0; ib<DD; ib+=16){
      #pragma unroll
      for (int z=0;z<4;z++){ int e = z*256+tid; int i=e>>6, j=e&63;
        aq[i][j] = Wq[(size_t)(ib+i)*DD + j0 + j];
        ak[i][j] = Wk[(size_t)(ib+i)*DD + d0 + j]; }
      __syncthreads();
      #pragma unroll
      for (int i=0;i<16;i++){
        float qv[4], kv[4];
        #pragma unroll
        for (int u=0;u<4;u++){ qv[u]=aq[i][ty*4+u]; kv[u]=ak[i][tx*4+u]; }
        #pragma unroll
        for (int jr=0;jr<4;jr++)
          #pragma unroll
          for (int dr=0;dr<4;dr++) acc[jr*4+dr] = fmaf(qv[jr], kv[dr], acc[jr*4+dr]);
      }
      __syncthreads();
    }
    #pragma unroll
    for (int jr=0;jr<4;jr++)
      #pragma unroll
      for (int dr=0;dr<4;dr++)
        g_AT[(size_t)(j0+ty*4+jr)*DD + d0+tx*4+dr] = acc[jr*4+dr]*SCALE;
  } else if (blk < 64){                // W2 tiles [d][i]
    __shared__ float wv[16][68], wu[16][68];
    int tn = blk-48, i0 = (tn>>2)*64, d0 = (tn&3)*64;
    int ty = tid>>4, tx = tid&15;
    float acc[16];
    #pragma unroll
    for (int z=0;z<16;z++) acc[z]=0.f;
    for (int jb=0; jb<DD; jb+=16){
      #pragma unroll
      for (int z=0;z<4;z++){ int e = z*256+tid; int jj=e>>6, ii=e&63;
        wv[jj][ii] = Wv[(size_t)(jb+jj)*DD + i0 + ii];
        wu[jj][ii] = Wu[(size_t)(d0+ii)*2*DD + DD + jb + jj]; }
      __syncthreads();
      #pragma unroll
      for (int jj=0;jj<16;jj++){
        float vv[4], uv[4];
        #pragma unroll
        for (int u=0;u<4;u++){ vv[u]=wv[jj][ty*4+u]; uv[u]=wu[jj][tx*4+u]; }
        #pragma unroll
        for (int ir=0;ir<4;ir++)
          #pragma unroll
          for (int dr=0;dr<4;dr++) acc[ir*4+dr] = fmaf(vv[ir], uv[dr], acc[ir*4+dr]);
      }
      __syncthreads();
    }
    #pragma unroll
    for (int ir=0;ir<4;ir++)
      #pragma unroll
      for (int dr=0;dr<4;dr++)
        g_W2[(size_t)(d0+tx*4+dr)*DD + i0+ty*4+ir] = acc[ir*4+dr];
  } else if (blk < 80){                // slot map clear
    int base = (blk-64)*2048;
    #pragma unroll
    for (int z=0;z<8;z++) g_slot[base + z*256 + tid] = -1;
  } else if (blk == 80){
    if (tid==0) g_gen2 = 0;
    if (tid < BB) g_ovcnt[tid] = 0;
    for (int i=tid;i<NB*32;i+=256) g_flag[i] = 0;
  } else if (blk == 81){               // avec
    __shared__ float bqs[DD];
    bqs[tid] = bq[tid]; __syncthreads();
    float acc = 0.f;
    #pragma unroll 4
    for (int i=0;i<DD;i++) acc = fmaf(Wk[(size_t)i*DD+tid], bqs[i], acc);
    g_avec[tid] = acc*SCALE;
  } else if (blk == 82){               // cvec
    __shared__ float bvs[DD];
    bvs[tid] = bv[tid]; __syncthreads();
    float acc = 0.f;
    #pragma unroll 4
    for (int j=0;j<DD;j++) acc = fmaf(Wu[(size_t)tid*2*DD + DD + j], bvs[j], acc);
    g_cvec[tid] = acc;
  }
}

// =================== init launch 2: qk / gx GEMMs ===================
__global__ void p_init2(const float* __restrict__ x, const float* __restrict__ bu){
  __shared__ float xt[64][17];
  __shared__ float wt[16][68];
  int blk = blockIdx.x, tid = threadIdx.x;
  int which = blk>>6;
  int r = blk&63;
  int s0 = (r>>2)*64, d0 = (r&3)*64;
  const float* W = which ? g_WuT1 : g_AT;
  int ty = tid>>4, tx = tid&15;
  float acc[16];
  #pragma unroll
  for (int z=0;z<16;z++) acc[z]=0.f;
  for (int jb=0; jb<DD; jb+=16){
    { int ss = tid>>2, jq = tid&3;
      float4 xv = *(const float4*)&x[(size_t)(s0+ss)*DD + jb + jq*4];
      xt[ss][jq*4+0]=xv.x; xt[ss][jq*4+1]=xv.y; xt[ss][jq*4+2]=xv.z; xt[ss][jq*4+3]=xv.w; }
    #pragma unroll
    for (int z=0;z<4;z++){ int e = z*256+tid; int jj=e>>6, dd=e&63;
      wt[jj][dd] = W[(size_t)(jb+jj)*DD + d0 + dd]; }
    __syncthreads();
    #pragma unroll
    for (int jj=0;jj<16;jj++){
      float xv[4], wv4[4];
      #pragma unroll
      for (int u=0;u<4;u++){ xv[u]=xt[ty*4+u][jj]; wv4[u]=wt[jj][tx*4+u]; }
      #pragma unroll
      for (int sr=0;sr<4;sr++)
        #pragma unroll
        for (int dr=0;dr<4;dr++) acc[sr*4+dr] = fmaf(xv[sr], wv4[dr], acc[sr*4+dr]);
    }
    __syncthreads();
  }
  float* dst = which ? g_gx : g_qk;
  const float* bias = which ? bu : g_avec;
  #pragma unroll
  for (int sr=0;sr<4;sr++){
    int s = s0 + ty*4 + sr;
    int b = s>>6, t = s&63;
    size_t ro = (size_t)(t*BB+b)*DD + d0 + tx*4;
    #pragma unroll
    for (int dr=0;dr<4;dr++) dst[ro+dr] = acc[sr*4+dr] + bias[d0+tx*4+dr];
  }
}

// =================== flag-array grid barrier (no atomics) ===================
__device__ __forceinline__ void gbar(int target){
  __syncthreads();
  int tid = threadIdx.x, blk = blockIdx.x;
  if (blk == 0){
    if (tid >= 1 && tid < NB){
      int v;
      do {
        asm volatile("ld.acquire.gpu.global.s32 %0, [%1];"
                     : "=r"(v) : "l"(&g_flag[tid*32]) : "memory");
      } while (v < target);
    }
    __syncthreads();
    if (tid == 0)
      asm volatile("st.release.gpu.global.s32 [%0], %1;"
                   :: "l"(&g_gen2), "r"(target) : "memory");
  } else {
    if (tid == 0){
      asm volatile("st.release.gpu.global.s32 [%0], %1;"
                   :: "l"(&g_flag[blk*32]), "r"(target) : "memory");
      int v;
      do {
        asm volatile("ld.acquire.gpu.global.s32 %0, [%1];"
                     : "=r"(v) : "l"(&g_gen2) : "memory");
      } while (v < target);
    }
    __syncthreads();
  }
}

__device__ __forceinline__ float dot4acc(float4 a, float4 b, float acc){
  acc = fmaf(a.x, b.x, acc);
  acc = fmaf(a.y, b.y, acc);
  acc = fmaf(a.z, b.z, acc);
  acc = fmaf(a.w, b.w, acc);
  return acc;
}

// =================== the persistent kernel (512 threads) ===================
__global__ void __launch_bounds__(NT, 1)
persist(const float* __restrict__ base, const float* __restrict__ x,
        const float* __restrict__ Wv, const float* __restrict__ bv,
        float* __restrict__ out){
  extern __shared__ float dsm[];
  float* rowsf = dsm;          // [16][256]
  float* qks   = dsm + 4096;   // [16][256]
  float* sbuf  = dsm + 8192;   // AB: spart[d][b] ; C2: h[j][b]

  __shared__ float sc[16][17];
  __shared__ __align__(16) float esm[16][16];   // [r][b]
  __shared__ int   dlist[256];
  __shared__ int   dcnt_s;
  __shared__ float warrv[8]; __shared__ int warri[8];
  __shared__ int   idxs_s[TK];
  __shared__ int   chosen_s;
  __shared__ __align__(16) float4 sred4[NT];
  __shared__ float zred[4];
  __shared__ __align__(16) float wrow[4*DD];
  __shared__ float cacc[16][4][9];
  __shared__ float sgate[16][2];
  __shared__ int   tk_s[BB*TK*3];
  __shared__ float zin_s[16];
  __shared__ float sbv[2], scv[2];

  int blk = blockIdx.x, tid = threadIdx.x;
  int m0 = blk*16;
  int wid = tid>>5, lane = tid&31;
  int dd0 = blk*2;

  // persistent smem loads
  for (int i=tid;i<16*DD;i+=NT) rowsf[i] = base[(size_t)m0*DD + i];
  {
    const float4* q4 = (const float4*)g_qk;
    float4* qd = (float4*)qks;
    for (int i=tid;i<1024;i+=NT) qd[i] = __ldg(&q4[i]);
  }
  { int i = tid; if (i < 2*DD){ wrow[i] = Wv[(size_t)dd0*DD + i]; wrow[2*DD+i] = g_W2[(size_t)dd0*DD + i]; } }
  if (tid<2){ sbv[tid] = bv[dd0+tid]; scv[tid] = g_cvec[dd0+tid]; }

  int bid = 0;
  for (int t=0;t<SS;t++){
    // ================= Phase AB =================
    if (tid==0) dcnt_s = 0;
    __syncthreads();
    if (tid < 256){
      int b = tid>>4, r = tid&15;
      int s = __ldcg(&g_slot[b*MM + m0 + r]);
      if (s >= 0){ int p = atomicAdd(&dcnt_s,1); dlist[p] = (b<<16)|(r<<12)|s; }
    }
    // score GEMM: warp wid owns (bq0,r0) 4x4 tile; lane splits K 32 ways
    {
      int bq0 = (wid&3)*4, r0 = (wid>>2)*4;
      int j0 = lane*8;
      float acc[16];
      #pragma unroll
      for (int z=0;z<16;z++) acc[z]=0.f;
      #pragma unroll
      for (int hh=0; hh<2; hh++){
        int jb = j0 + hh*4;
        float4 qa[4], ra[4];
        #pragma unroll
        for (int u=0;u<4;u++){
          qa[u] = *(const float4*)&qks[(bq0+u)*256 + jb];
          ra[u] = *(const float4*)&rowsf[(r0+u)*256 + jb];
        }
        #pragma unroll
        for (int bi=0;bi<4;bi++)
          #pragma unroll
          for (int ri=0;ri<4;ri++)
            acc[bi*4+ri] = dot4acc(qa[bi], ra[ri], acc[bi*4+ri]);
      }
      #pragma unroll
      for (int off=16; off; off>>=1){
        #pragma unroll
        for (int z=0;z<16;z++) acc[z] += __shfl_xor_sync(0xffffffffu, acc[z], off);
      }
      if (lane==0){
        #pragma unroll
        for (int bi=0;bi<4;bi++)
          #pragma unroll
          for (int ri=0;ri<4;ri++) sc[bq0+bi][r0+ri] = acc[bi*4+ri];
      }
    }
    __syncthreads();
    int dn = dcnt_s;
    // dirty score fixes (16 warps over entries)
    for (int e=wid; e<dn; e+=16){
      int pk = dlist[e]; int eb = pk>>16, er = (pk>>12)&15, es = pk&0xfff;
      const float* ov = g_ovl + ((size_t)eb*OV + es)*DD;
      float a2 = 0.f;
      #pragma unroll
      for (int k=0;k<8;k++) a2 = fmaf(__ldcg(&ov[lane+32*k]), qks[eb*256 + lane+32*k], a2);
      #pragma unroll
      for (int off=16; off; off>>=1) a2 += __shfl_xor_sync(0xffffffffu, a2, off);
      if (lane==0) sc[eb][er] = a2;
    }
    __syncthreads();
    // exp + psum (warps 0-7) ; per-chunk top-8 candidates (warps 8-15)
    if (tid < 256){
      int b = tid>>4, r = tid&15;
      float e = expf(sc[b][r]);
      esm[r][b] = e;
      float ps = e;
      #pragma unroll
      for (int off=8; off; off>>=1) ps += __shfl_xor_sync(0xffffffffu, ps, off);
      if (r==0) __stcg(&g_psum[blk*16 + b], ps);
    } else if (t < SS-1){
      int w2 = wid - 8;
      int hw = lane>>4, hl = lane&15;
      int b = w2*2 + hw;
      float v = sc[b][hl];
      int ix = m0 + hl;
      #pragma unroll
      for (int round=0; round<TK; round++){
        float bv2 = v; int bix = ix;
        #pragma unroll
        for (int off=8; off; off>>=1){
          float ovv = __shfl_xor_sync(0xffffffffu, bv2, off);
          int   oi  = __shfl_xor_sync(0xffffffffu, bix, off);
          if (ovv > bv2 || (ovv==bv2 && oi<bix)){ bv2=ovv; bix=oi; }
        }
        if (hl==0){
          __stcg(&g_cv[(blk*BB+b)*TK + round], bv2);
          __stcg(&g_ci[(blk*BB+b)*TK + round], bix);
        }
        if (ix == bix) v = -FLT_MAX;
      }
    }
    __syncthreads();
    // base partials: 2 threads per d
    {
      int d = tid>>1, half = tid&1;
      float4 A0 = make_float4(0.f,0.f,0.f,0.f), A1 = A0;
      #pragma unroll
      for (int r=0;r<16;r++){
        float4 e0 = *(const float4*)&esm[r][half*8];
        float4 e1 = *(const float4*)&esm[r][half*8+4];
        float rr = rowsf[r*256 + d];
        A0.x = fmaf(e0.x, rr, A0.x); A0.y = fmaf(e0.y, rr, A0.y);
        A0.z = fmaf(e0.z, rr, A0.z); A0.w = fmaf(e0.w, rr, A0.w);
        A1.x = fmaf(e1.x, rr, A1.x); A1.y = fmaf(e1.y, rr, A1.y);
        A1.z = fmaf(e1.z, rr, A1.z); A1.w = fmaf(e1.w, rr, A1.w);
      }
      *(float4*)&sbuf[d*16 + half*8]     = A0;
      *(float4*)&sbuf[d*16 + half*8 + 4] = A1;
    }
    __syncthreads();
    // dirty partial corrections: warp w owns batch eb==w (register accumulate, no atomics)
    {
      float corr[8] = {0.f,0.f,0.f,0.f,0.f,0.f,0.f,0.f};
      bool any = false;
      for (int e=0;e<dn;e++){
        int pk = dlist[e];
        if ((pk>>16) == wid){
          int er = (pk>>12)&15, es = pk&0xfff;
          float ev = esm[er][wid];
          const float* ov = g_ovl + ((size_t)wid*OV + es)*DD;
          any = true;
          #pragma unroll
          for (int k=0;k<8;k++){
            int d = lane+32*k;
            corr[k] = fmaf(ev, __ldcg(&ov[d]) - rowsf[er*256 + d], corr[k]);
          }
        }
      }
      if (any){
        #pragma unroll
        for (int k=0;k<8;k++){ int d = lane+32*k; sbuf[d*16 + wid] += corr[k]; }
      }
    }
    __syncthreads();
    // store partials [k][d][b]
    {
      int d = tid>>1, half = tid&1;
      float4* gp4 = (float4*)g_part;
      __stcg(&gp4[((size_t)blk*256 + d)*4 + half*2 + 0], *(const float4*)&sbuf[d*16 + half*8]);
      __stcg(&gp4[((size_t)blk*256 + d)*4 + half*2 + 1], *(const float4*)&sbuf[d*16 + half*8 + 4]);
    }
    gbar(++bid);

    // ================= Phase C1 =================
    {
      const float4* gp4 = (const float4*)g_part;
      int q = tid&7, kk = tid>>3;
      int dj = q>>2, q2 = q&3;
      float4 a4 = make_float4(0.f,0.f,0.f,0.f);
      #pragma unroll
      for (int p=0;p<2;p++){
        int k = kk + p*64;
        float4 v = __ldcg(&gp4[((size_t)k*256 + dd0 + dj)*4 + q2]);
        a4.x += v.x; a4.y += v.y; a4.z += v.z; a4.w += v.w;
      }
      sred4[tid] = a4;
      __syncthreads();
      #pragma unroll
      for (int off=256; off>=8; off>>=1){
        if (tid < off){
          float4 o = sred4[tid+off]; float4 m = sred4[tid];
          m.x+=o.x; m.y+=o.y; m.z+=o.z; m.w+=o.w;
          sred4[tid] = m;
        }
        __syncthreads();
      }
      if (tid < 8) __stcg(&((float4*)g_h)[dd0*4 + tid], sred4[tid]);
    }
    if (t+1 < SS){
      const float4* q4 = (const float4*)(g_qk + (size_t)(t+1)*BB*DD);
      float4* qd = (float4*)qks;
      for (int i=tid;i<1024;i+=NT) qd[i] = __ldg(&q4[i]);
    }
    if (blk < BB){
      int b2 = blk;
      float zp = (tid < NB) ? __ldcg(&g_psum[tid*16 + b2]) : 0.f;
      #pragma unroll
      for (int off=16; off; off>>=1) zp += __shfl_xor_sync(0xffffffffu, zp, off);
      if (lane==0 && wid<4) zred[wid] = zp;
      __syncthreads();
      if (tid==0) __stcg(&g_zinv[b2], 1.0f/(zred[0]+zred[1]+zred[2]+zred[3]));
      if (t < SS-1){
        // merge 128x8 candidates
        float vloc[4]; int ixl[4];
        if (tid < 256){
          int kk = tid>>1, q0 = (tid&1)*4;
          float4 cv4 = __ldcg((const float4*)&g_cv[(size_t)(kk*BB + b2)*TK + q0]);
          int4   ci4 = __ldcg((const int4*)  &g_ci[(size_t)(kk*BB + b2)*TK + q0]);
          vloc[0]=cv4.x; vloc[1]=cv4.y; vloc[2]=cv4.z; vloc[3]=cv4.w;
          ixl[0]=ci4.x;  ixl[1]=ci4.y;  ixl[2]=ci4.z;  ixl[3]=ci4.w;
        }
        for (int round=0; round<TK; round++){
          if (tid < 256){
            float v = -FLT_MAX; int bi2 = MM;
            #pragma unroll
            for (int z=0;z<4;z++){
              if (vloc[z] > v || (vloc[z]==v && ixl[z]<bi2)){ v=vloc[z]; bi2=ixl[z]; }
            }
            #pragma unroll
            for (int off=16; off; off>>=1){
              float ov2 = __shfl_xor_sync(0xffffffffu, v, off);
              int   oi  = __shfl_xor_sync(0xffffffffu, bi2, off);
              if (ov2 > v || (ov2==v && oi<bi2)){ v=ov2; bi2=oi; }
            }
            if (lane==0){ warrv[wid]=v; warri[wid]=bi2; }
          }
          __syncthreads();
          if (tid==0){
            float bv2 = warrv[0]; int bj = warri[0];
            for (int w=1;w<8;w++){
              if (warrv[w]>bv2 || (warrv[w]==bv2 && warri[w]<bj)){ bv2=warrv[w]; bj=warri[w]; }
            }
            idxs_s[round] = bj; chosen_s = bj;
          }
          __syncthreads();
          if (tid < 256){
            int ch = chosen_s;
            #pragma unroll
            for (int z=0;z<4;z++) if (ixl[z]==ch) vloc[z] = -FLT_MAX;
          }
        }
        // parallel slot assignment (warp 0)
        if (tid < 32){
          bool valid = lane < TK;
          int row = idxs_s[valid ? lane : 0];
          int s = valid ? __ldcg(&g_slot[b2*MM + row]) : 0;
          unsigned nm = __ballot_sync(0xffffffffu, valid && s < 0);
          int cnt0 = 0;
          if (lane==0) cnt0 = __ldcg(&g_ovcnt[b2]);
          cnt0 = __shfl_sync(0xffffffffu, cnt0, 0);
          if (valid){
            int prev = s, slot = s;
            if (s < 0){
              slot = cnt0 + __popc(nm & ((1u<<lane)-1));
              __stcg(&g_slot[b2*MM + row], slot);
            }
            __stcg(&g_tk[b2*24 + lane*3 + 0], row);
            __stcg(&g_tk[b2*24 + lane*3 + 1], prev);
            __stcg(&g_tk[b2*24 + lane*3 + 2], slot);
          }
          if (lane==0) __stcg(&g_ovcnt[b2], cnt0 + __popc(nm));
        }
      }
    }
    gbar(++bid);

    // ================= Phase C2 =================
    {
      const float4* h4g = (const float4*)g_h;
      float4* s4 = (float4*)sbuf;
      for (int i=tid;i<1024;i+=NT) s4[i] = __ldcg(&h4g[i]);
      if (tid < 16) zin_s[tid] = __ldcg(&g_zinv[tid]);
      if (t < SS-1){
        for (int i=tid;i<BB*TK*3;i+=NT) tk_s[i] = __ldcg(&g_tk[i]);
      }
      __syncthreads();
      if (tid < 256){
        int b = tid&15, jseg = tid>>4;
        float a0=0.f, a1=0.f, a2=0.f, a3=0.f;
        #pragma unroll
        for (int jj=0;jj<16;jj++){
          int j = jseg*16 + jj;
          float hv = sbuf[j*16 + b];
          a0 = fmaf(wrow[j],        hv, a0);
          a1 = fmaf(wrow[256 + j],  hv, a1);
          a2 = fmaf(wrow[512 + j],  hv, a2);
          a3 = fmaf(wrow[768 + j],  hv, a3);
        }
        a0 += __shfl_xor_sync(0xffffffffu, a0, 16);
        a1 += __shfl_xor_sync(0xffffffffu, a1, 16);
        a2 += __shfl_xor_sync(0xffffffffu, a2, 16);
        a3 += __shfl_xor_sync(0xffffffffu, a3, 16);
        if ((tid&16)==0){
          cacc[b][0][wid]=a0; cacc[b][1][wid]=a1; cacc[b][2][wid]=a2; cacc[b][3][wid]=a3;
        }
      }
      __syncthreads();
      if (tid < 64){
        int b = tid&15, o = tid>>4;
        float s = 0.f;
        #pragma unroll
        for (int w=0;w<8;w++) s += cacc[b][o][w];
        float zi = zin_s[b];
        if (o < 2){
          out[((size_t)b*SS+t)*DD + dd0 + o] = s*zi + sbv[o];
        } else {
          int di = o-2;
          float gg = s*zi + scv[di] + __ldg(&g_gx[((size_t)t*BB+b)*DD + dd0 + di]);
          sgate[b][di] = 1.0f/(1.0f+expf(-gg));
        }
      }
      __syncthreads();
      if (t < SS-1 && tid < 256){
        int ent = tid>>1, di = tid&1;
        int b = ent>>3, i = ent&7;
        int row  = tk_s[(b*TK+i)*3 + 0];
        int prev = tk_s[(b*TK+i)*3 + 1];
        int slot = tk_s[(b*TK+i)*3 + 2];
        int d = dd0 + di;
        float old = (prev < 0) ? __ldg(&base[(size_t)row*DD + d])
                               : __ldcg(&g_ovl[((size_t)b*OV + prev)*DD + d]);
        float g = sgate[b][di];
        float xd = __ldg(&x[((size_t)b*SS+t)*DD + d]);
        __stcg(&g_ovl[((size_t)b*OV + slot)*DD + d], old + g*(xd - old));
      }
    }
    gbar(++bid);
  }
}

// =================== launch ===================
extern "C" void kernel_launch(void* const* d_in, const int* in_sizes, int n_in,
                              void* d_out, int out_size){
  const float* x      = (const float*)d_in[0];
  const float* memory = (const float*)d_in[1];
  const float* Wq     = (const float*)d_in[2];
  const float* bq     = (const float*)d_in[3];
  const float* Wk     = (const float*)d_in[4];
  // bk contributes only a softmax-invariant constant -> dropped
  const float* Wv     = (const float*)d_in[6];
  const float* bv     = (const float*)d_in[7];
  const float* Wu     = (const float*)d_in[8];
  const float* bu     = (const float*)d_in[9];
  float* out = (float*)d_out;

  static int attr_done = 0;
  if (!attr_done){
    cudaFuncSetAttribute(persist, cudaFuncAttributeMaxDynamicSharedMemorySize, 49152);
    attr_done = 1;
  }

  p_init1<<<NB, 256>>>(Wq, bq, Wk, Wv, bv, Wu);
  p_init2<<<NB, 256>>>(x, bu);
  persist<<<NB, NT, 49152>>>(memory, x, Wv, bv, out);
}

// round 13
// speedup vs baseline: 1.6153x; 1.1313x over previous
#include <cuda_runtime.h>
#include <math.h>
#include <float.h>

#define BB 16
#define SS 64
#define MM 2048
#define DD 256
#define TK 8
#define OV 512
#define NB 128
#define NT 512
#define SCALE 0.0625f

// ---- persistent state (no runtime allocs) ----
__device__ float g_ovl[BB*OV*DD];
__device__ int   g_slot[BB*MM];
__device__ int   g_ovcnt[BB];
__device__ __align__(16) float g_qk[SS*BB*DD];
__device__ __align__(16) float g_gx[SS*BB*DD];
__device__ float g_AT[DD*DD];
__device__ float g_avec[DD];
__device__ float g_WuT1[DD*DD];
__device__ float g_W2[DD*DD];
__device__ float g_cvec[DD];
__device__ __align__(16) float g_psum[BB*NB];      // [b][k]
__device__ __align__(16) float g_part[NB*DD*BB];   // [k][d][b]
__device__ __align__(16) float g_h[DD*BB];         // [j][b]
__device__ __align__(16) unsigned long long g_ck[NB*BB*TK];  // packed candidates
__device__ int   g_tk[BB*TK*3];
__device__ int   g_flag[NB*32];
__device__ int   g_gen2;

// =================== init launch 1 ===================
__global__ void p_init1(const float* __restrict__ Wq, const float* __restrict__ bq,
                        const float* __restrict__ Wk, const float* __restrict__ Wv,
                        const float* __restrict__ bv, const float* __restrict__ Wu){
  int blk = blockIdx.x, tid = threadIdx.x;
  if (blk < 32){
    int base = blk*2048;
    #pragma unroll
    for (int z=0;z<8;z++){ int e = base + z*256 + tid; int d = e>>8, j = e&255;
      g_WuT1[j*DD+d] = Wu[(size_t)d*2*DD + j]; }
  } else if (blk < 48){                // A tiles: g_AT[j][d]
    __shared__ float aq[16][68], ak[16][68];
    int tn = blk-32, j0 = (tn>>2)*64, d0 = (tn&3)*64;
    int ty = tid>>4, tx = tid&15;
    float acc[16];
    #pragma unroll
    for (int z=0;z<16;z++) acc[z]=0.f;
    for (int ib=0; ib<DD; ib+=16){
      #pragma unroll
      for (int z=0;z<4;z++){ int e = z*256+tid; int i=e>>6, j=e&63;
        aq[i][j] = Wq[(size_t)(ib+i)*DD + j0 + j];
        ak[i][j] = Wk[(size_t)(ib+i)*DD + d0 + j]; }
      __syncthreads();
      #pragma unroll
      for (int i=0;i<16;i++){
        float qv[4], kv[4];
        #pragma unroll
        for (int u=0;u<4;u++){ qv[u]=aq[i][ty*4+u]; kv[u]=ak[i][tx*4+u]; }
        #pragma unroll
        for (int jr=0;jr<4;jr++)
          #pragma unroll
          for (int dr=0;dr<4;dr++) acc[jr*4+dr] = fmaf(qv[jr], kv[dr], acc[jr*4+dr]);
      }
      __syncthreads();
    }
    #pragma unroll
    for (int jr=0;jr<4;jr++)
      #pragma unroll
      for (int dr=0;dr<4;dr++)
        g_AT[(size_t)(j0+ty*4+jr)*DD + d0+tx*4+dr] = acc[jr*4+dr]*SCALE;
  } else if (blk < 64){                // W2 tiles [d][i]
    __shared__ float wv[16][68], wu[16][68];
    int tn = blk-48, i0 = (tn>>2)*64, d0 = (tn&3)*64;
    int ty = tid>>4, tx = tid&15;
    float acc[16];
    #pragma unroll
    for (int z=0;z<16;z++) acc[z]=0.f;
    for (int jb=0; jb<DD; jb+=16){
      #pragma unroll
      for (int z=0;z<4;z++){ int e = z*256+tid; int jj=e>>6, ii=e&63;
        wv[jj][ii] = Wv[(size_t)(jb+jj)*DD + i0 + ii];
        wu[jj][ii] = Wu[(size_t)(d0+ii)*2*DD + DD + jb + jj]; }
      __syncthreads();
      #pragma unroll
      for (int jj=0;jj<16;jj++){
        float vv[4], uv[4];
        #pragma unroll
        for (int u=0;u<4;u++){ vv[u]=wv[jj][ty*4+u]; uv[u]=wu[jj][tx*4+u]; }
        #pragma unroll
        for (int ir=0;ir<4;ir++)
          #pragma unroll
          for (int dr=0;dr<4;dr++) acc[ir*4+dr] = fmaf(vv[ir], uv[dr], acc[ir*4+dr]);
      }
      __syncthreads();
    }
    #pragma unroll
    for (int ir=0;ir<4;ir++)
      #pragma unroll
      for (int dr=0;dr<4;dr++)
        g_W2[(size_t)(d0+tx*4+dr)*DD + i0+ty*4+ir] = acc[ir*4+dr];
  } else if (blk < 80){                // slot map clear
    int base = (blk-64)*2048;
    #pragma unroll
    for (int z=0;z<8;z++) g_slot[base + z*256 + tid] = -1;
  } else if (blk == 80){
    if (tid==0) g_gen2 = 0;
    if (tid < BB) g_ovcnt[tid] = 0;
    for (int i=tid;i<NB*32;i+=256) g_flag[i] = 0;
  } else if (blk == 81){               // avec
    __shared__ float bqs[DD];
    bqs[tid] = bq[tid]; __syncthreads();
    float acc = 0.f;
    #pragma unroll 4
    for (int i=0;i<DD;i++) acc = fmaf(Wk[(size_t)i*DD+tid], bqs[i], acc);
    g_avec[tid] = acc*SCALE;
  } else if (blk == 82){               // cvec
    __shared__ float bvs[DD];
    bvs[tid] = bv[tid]; __syncthreads();
    float acc = 0.f;
    #pragma unroll 4
    for (int j=0;j<DD;j++) acc = fmaf(Wu[(size_t)tid*2*DD + DD + j], bvs[j], acc);
    g_cvec[tid] = acc;
  }
}

// =================== init launch 2: qk / gx GEMMs ===================
__global__ void p_init2(const float* __restrict__ x, const float* __restrict__ bu){
  __shared__ float xt[64][17];
  __shared__ float wt[16][68];
  int blk = blockIdx.x, tid = threadIdx.x;
  int which = blk>>6;
  int r = blk&63;
  int s0 = (r>>2)*64, d0 = (r&3)*64;
  const float* W = which ? g_WuT1 : g_AT;
  int ty = tid>>4, tx = tid&15;
  float acc[16];
  #pragma unroll
  for (int z=0;z<16;z++) acc[z]=0.f;
  for (int jb=0; jb<DD; jb+=16){
    { int ss = tid>>2, jq = tid&3;
      float4 xv = *(const float4*)&x[(size_t)(s0+ss)*DD + jb + jq*4];
      xt[ss][jq*4+0]=xv.x; xt[ss][jq*4+1]=xv.y; xt[ss][jq*4+2]=xv.z; xt[ss][jq*4+3]=xv.w; }
    #pragma unroll
    for (int z=0;z<4;z++){ int e = z*256+tid; int jj=e>>6, dd=e&63;
      wt[jj][dd] = W[(size_t)(jb+jj)*DD + d0 + dd]; }
    __syncthreads();
    #pragma unroll
    for (int jj=0;jj<16;jj++){
      float xv[4], wv4[4];
      #pragma unroll
      for (int u=0;u<4;u++){ xv[u]=xt[ty*4+u][jj]; wv4[u]=wt[jj][tx*4+u]; }
      #pragma unroll
      for (int sr=0;sr<4;sr++)
        #pragma unroll
        for (int dr=0;dr<4;dr++) acc[sr*4+dr] = fmaf(xv[sr], wv4[dr], acc[sr*4+dr]);
    }
    __syncthreads();
  }
  float* dst = which ? g_gx : g_qk;
  const float* bias = which ? bu : g_avec;
  #pragma unroll
  for (int sr=0;sr<4;sr++){
    int s = s0 + ty*4 + sr;
    int b = s>>6, t = s&63;
    size_t ro = (size_t)(t*BB+b)*DD + d0 + tx*4;
    #pragma unroll
    for (int dr=0;dr<4;dr++) dst[ro+dr] = acc[sr*4+dr] + bias[d0+tx*4+dr];
  }
}

// =================== flag-array grid barrier (no atomics) ===================
__device__ __forceinline__ void gbar(int target){
  __syncthreads();
  int tid = threadIdx.x, blk = blockIdx.x;
  if (blk == 0){
    if (tid >= 1 && tid < NB){
      int v;
      do {
        asm volatile("ld.acquire.gpu.global.s32 %0, [%1];"
                     : "=r"(v) : "l"(&g_flag[tid*32]) : "memory");
      } while (v < target);
    }
    __syncthreads();
    if (tid == 0)
      asm volatile("st.release.gpu.global.s32 [%0], %1;"
                   :: "l"(&g_gen2), "r"(target) : "memory");
  } else {
    if (tid == 0){
      asm volatile("st.release.gpu.global.s32 [%0], %1;"
                   :: "l"(&g_flag[blk*32]), "r"(target) : "memory");
      int v;
      do {
        asm volatile("ld.acquire.gpu.global.s32 %0, [%1];"
                     : "=r"(v) : "l"(&g_gen2) : "memory");
      } while (v < target);
    }
    __syncthreads();
  }
}

__device__ __forceinline__ float dot4acc(float4 a, float4 b, float acc){
  acc = fmaf(a.x, b.x, acc);
  acc = fmaf(a.y, b.y, acc);
  acc = fmaf(a.z, b.z, acc);
  acc = fmaf(a.w, b.w, acc);
  return acc;
}

// =================== the persistent kernel (512 threads) ===================
__global__ void __launch_bounds__(NT, 1)
persist(const float* __restrict__ base, const float* __restrict__ x,
        const float* __restrict__ Wv, const float* __restrict__ bv,
        float* __restrict__ out){
  extern __shared__ float dsm[];
  float* rowsf = dsm;          // [16][256]
  float* qks   = dsm + 4096;   // [16][256]
  float* sbuf  = dsm + 8192;   // AB: spart[d][b] ; C2: h[j][b]

  __shared__ float sc[16][17];
  __shared__ __align__(16) float esm[16][16];   // [r][b]
  __shared__ int   dlist[256];
  __shared__ int   dcnt_s;
  __shared__ unsigned long long warrk[8];
  __shared__ unsigned long long chosen_k;
  __shared__ int   idxs_s[TK];
  __shared__ __align__(16) float4 hred4[128];
  __shared__ __align__(16) float wrow[4*DD];
  __shared__ float cacc[16][4][17];
  __shared__ float sgate[16][2];
  __shared__ int   tk_s[BB*TK*3];
  __shared__ float zin_s[16];
  __shared__ float sbv[2], scv[2];

  int blk = blockIdx.x, tid = threadIdx.x;
  int m0 = blk*16;
  int wid = tid>>5, lane = tid&31;
  int dd0 = blk*2;

  // persistent smem loads
  for (int i=tid;i<16*DD;i+=NT) rowsf[i] = base[(size_t)m0*DD + i];
  {
    const float4* q4 = (const float4*)g_qk;
    float4* qd = (float4*)qks;
    for (int i=tid;i<1024;i+=NT) qd[i] = __ldg(&q4[i]);
  }
  { int i = tid; if (i < 2*DD){ wrow[i] = Wv[(size_t)dd0*DD + i]; wrow[2*DD+i] = g_W2[(size_t)dd0*DD + i]; } }
  if (tid<2){ sbv[tid] = bv[dd0+tid]; scv[tid] = g_cvec[dd0+tid]; }

  int bid = 0;
  for (int t=0;t<SS;t++){
    // ================= Phase AB =================
    if (tid==0) dcnt_s = 0;
    __syncthreads();
    if (tid < 256){
      int b = tid>>4, r = tid&15;
      int s = __ldcg(&g_slot[b*MM + m0 + r]);
      if (s >= 0){ int p = atomicAdd(&dcnt_s,1); dlist[p] = (b<<16)|(r<<12)|s; }
    }
    // score GEMM: warp wid owns (bq0,r0) 4x4 tile; lane splits K 32 ways;
    // reduce-and-swap butterfly: 16 SHFL total
    {
      int bq0 = (wid&3)*4, r0 = (wid>>2)*4;
      int j0 = lane*8;
      float acc[16];
      #pragma unroll
      for (int z=0;z<16;z++) acc[z]=0.f;
      #pragma unroll
      for (int hh=0; hh<2; hh++){
        int jb = j0 + hh*4;
        float4 qa[4], ra[4];
        #pragma unroll
        for (int u=0;u<4;u++){
          qa[u] = *(const float4*)&qks[(bq0+u)*256 + jb];
          ra[u] = *(const float4*)&rowsf[(r0+u)*256 + jb];
        }
        #pragma unroll
        for (int bi=0;bi<4;bi++)
          #pragma unroll
          for (int ri=0;ri<4;ri++)
            acc[bi*4+ri] = dot4acc(qa[bi], ra[ri], acc[bi*4+ri]);
      }
      // level off=16 (keep 8)
      {
        bool hi = (lane & 16);
        #pragma unroll
        for (int z=0;z<8;z++){
          float send = hi ? acc[z] : acc[z+8];
          float r = __shfl_xor_sync(0xffffffffu, send, 16);
          acc[z] = (hi ? acc[z+8] : acc[z]) + r;
        }
      }
      { // off=8 (keep 4)
        bool hi = (lane & 8);
        #pragma unroll
        for (int z=0;z<4;z++){
          float send = hi ? acc[z] : acc[z+4];
          float r = __shfl_xor_sync(0xffffffffu, send, 8);
          acc[z] = (hi ? acc[z+4] : acc[z]) + r;
        }
      }
      { // off=4 (keep 2)
        bool hi = (lane & 4);
        #pragma unroll
        for (int z=0;z<2;z++){
          float send = hi ? acc[z] : acc[z+2];
          float r = __shfl_xor_sync(0xffffffffu, send, 4);
          acc[z] = (hi ? acc[z+2] : acc[z]) + r;
        }
      }
      { // off=2 (keep 1)
        bool hi = (lane & 2);
        float send = hi ? acc[0] : acc[1];
        float r = __shfl_xor_sync(0xffffffffu, send, 2);
        acc[0] = (hi ? acc[1] : acc[0]) + r;
      }
      acc[0] += __shfl_xor_sync(0xffffffffu, acc[0], 1);
      if ((lane & 1) == 0){
        int z = (lane>>1) & 15;
        sc[bq0 + (z>>2)][r0 + (z&3)] = acc[0];
      }
    }
    __syncthreads();
    int dn = dcnt_s;
    // dirty score fixes (16 warps over entries)
    for (int e=wid; e<dn; e+=16){
      int pk = dlist[e]; int eb = pk>>16, er = (pk>>12)&15, es = pk&0xfff;
      const float* ov = g_ovl + ((size_t)eb*OV + es)*DD;
      float a2 = 0.f;
      #pragma unroll
      for (int k=0;k<8;k++) a2 = fmaf(__ldcg(&ov[lane+32*k]), qks[eb*256 + lane+32*k], a2);
      #pragma unroll
      for (int off=16; off; off>>=1) a2 += __shfl_xor_sync(0xffffffffu, a2, off);
      if (lane==0) sc[eb][er] = a2;
    }
    __syncthreads();
    // exp + psum (warps 0-7) ; candidate bitonic top-8 (warps 8-15)
    if (tid < 256){
      int b = tid>>4, r = tid&15;
      float e = expf(sc[b][r]);
      esm[r][b] = e;
      float ps = e;
      #pragma unroll
      for (int off=8; off; off>>=1) ps += __shfl_xor_sync(0xffffffffu, ps, off);
      if (r==0) __stcg(&g_psum[b*NB + blk], ps);
    } else if (t < SS-1){
      int w2 = wid - 8;
      int hw = lane>>4, l4 = lane&15;
      int b = w2*2 + hw;
      float v = sc[b][l4];
      unsigned u = __float_as_uint(v);
      u = (u & 0x80000000u) ? ~u : (u | 0x80000000u);
      unsigned long long key = ((unsigned long long)u << 32) | (unsigned)(MM - (m0 + l4));
      #pragma unroll
      for (int k2=2; k2<=16; k2<<=1){
        #pragma unroll
        for (int j=k2>>1; j>0; j>>=1){
          unsigned long long o = __shfl_xor_sync(0xffffffffu, key, j);
          bool keep_max = ((l4 & k2)==0) == ((l4 & j)==0);
          key = keep_max ? (key > o ? key : o) : (key < o ? key : o);
        }
      }
      if (l4 < 8) __stcg(&g_ck[(size_t)(blk*BB+b)*TK + l4], key);
    }
    __syncthreads();
    // base partials: 2 threads per d
    {
      int d = tid>>1, half = tid&1;
      float4 A0 = make_float4(0.f,0.f,0.f,0.f), A1 = A0;
      #pragma unroll
      for (int r=0;r<16;r++){
        float4 e0 = *(const float4*)&esm[r][half*8];
        float4 e1 = *(const float4*)&esm[r][half*8+4];
        float rr = rowsf[r*256 + d];
        A0.x = fmaf(e0.x, rr, A0.x); A0.y = fmaf(e0.y, rr, A0.y);
        A0.z = fmaf(e0.z, rr, A0.z); A0.w = fmaf(e0.w, rr, A0.w);
        A1.x = fmaf(e1.x, rr, A1.x); A1.y = fmaf(e1.y, rr, A1.y);
        A1.z = fmaf(e1.z, rr, A1.z); A1.w = fmaf(e1.w, rr, A1.w);
      }
      *(float4*)&sbuf[d*16 + half*8]     = A0;
      *(float4*)&sbuf[d*16 + half*8 + 4] = A1;
    }
    __syncthreads();
    // dirty partial corrections: warp w owns batch eb==w
    {
      float corr[8] = {0.f,0.f,0.f,0.f,0.f,0.f,0.f,0.f};
      bool any = false;
      for (int e=0;e<dn;e++){
        int pk = dlist[e];
        if ((pk>>16) == wid){
          int er = (pk>>12)&15, es = pk&0xfff;
          float ev = esm[er][wid];
          const float* ov = g_ovl + ((size_t)wid*OV + es)*DD;
          any = true;
          #pragma unroll
          for (int k=0;k<8;k++){
            int d = lane+32*k;
            corr[k] = fmaf(ev, __ldcg(&ov[d]) - rowsf[er*256 + d], corr[k]);
          }
        }
      }
      if (any){
        #pragma unroll
        for (int k=0;k<8;k++){ int d = lane+32*k; sbuf[d*16 + wid] += corr[k]; }
      }
    }
    __syncthreads();
    // store partials [k][d][b]
    {
      int d = tid>>1, half = tid&1;
      float4* gp4 = (float4*)g_part;
      __stcg(&gp4[((size_t)blk*256 + d)*4 + half*2 + 0], *(const float4*)&sbuf[d*16 + half*8]);
      __stcg(&gp4[((size_t)blk*256 + d)*4 + half*2 + 1], *(const float4*)&sbuf[d*16 + half*8 + 4]);
    }
    gbar(++bid);

    // ================= Phase C1 =================
    // h reduce for this block's d-chunk: 2 shfl levels + small tree
    {
      const float4* gp4 = (const float4*)g_part;
      int q = tid&7, kg = tid>>3;   // kg 0..63
      float4 a4 = __ldcg(&gp4[((size_t)kg*256 + dd0 + (q>>2))*4 + (q&3)]);
      float4 b4 = __ldcg(&gp4[((size_t)(kg+64)*256 + dd0 + (q>>2))*4 + (q&3)]);
      a4.x += b4.x; a4.y += b4.y; a4.z += b4.z; a4.w += b4.w;
      #pragma unroll
      for (int off=8; off<=16; off<<=1){
        a4.x += __shfl_xor_sync(0xffffffffu, a4.x, off);
        a4.y += __shfl_xor_sync(0xffffffffu, a4.y, off);
        a4.z += __shfl_xor_sync(0xffffffffu, a4.z, off);
        a4.w += __shfl_xor_sync(0xffffffffu, a4.w, off);
      }
      if (lane < 8) hred4[wid*8 + lane] = a4;
      __syncthreads();
      if (tid < 64){ float4 u=hred4[tid], v=hred4[tid+64];
        u.x+=v.x; u.y+=v.y; u.z+=v.z; u.w+=v.w; hred4[tid]=u; }
      __syncthreads();
      if (tid < 32){ float4 u=hred4[tid], v=hred4[tid+32];
        u.x+=v.x; u.y+=v.y; u.z+=v.z; u.w+=v.w; hred4[tid]=u; }
      __syncthreads();
      if (tid < 16){ float4 u=hred4[tid], v=hred4[tid+16];
        u.x+=v.x; u.y+=v.y; u.z+=v.z; u.w+=v.w; hred4[tid]=u; }
      __syncthreads();
      if (tid < 8){ float4 u=hred4[tid], v=hred4[tid+8];
        u.x+=v.x; u.y+=v.y; u.z+=v.z; u.w+=v.w;
        __stcg(&((float4*)g_h)[dd0*4 + tid], u); }
    }
    // local 1/Z for all 16 batches (every block; coalesced psum[b][k])
    {
      const float4* ps4 = (const float4*)&g_psum[wid*NB];
      float4 p4 = __ldcg(&ps4[lane]);
      float zp = (p4.x+p4.y)+(p4.z+p4.w);
      #pragma unroll
      for (int off=16; off; off>>=1) zp += __shfl_xor_sync(0xffffffffu, zp, off);
      if (lane==0) zin_s[wid] = 1.0f/zp;
    }
    if (t+1 < SS){
      const float4* q4 = (const float4*)(g_qk + (size_t)(t+1)*BB*DD);
      float4* qd = (float4*)qks;
      for (int i=tid;i<1024;i+=NT) qd[i] = __ldg(&q4[i]);
    }
    if (blk < BB && t < SS-1){
      int b2 = blk;
      // merge 128x8 packed candidates
      unsigned long long kloc[4];
      if (tid < 256){
        int kk = tid>>1, q0 = (tid&1)*4;
        const unsigned long long* src = &g_ck[(size_t)(kk*BB + b2)*TK + q0];
        kloc[0]=__ldcg(&src[0]); kloc[1]=__ldcg(&src[1]);
        kloc[2]=__ldcg(&src[2]); kloc[3]=__ldcg(&src[3]);
      } else {
        kloc[0]=kloc[1]=kloc[2]=kloc[3]=0ull;
      }
      for (int round=0; round<TK; round++){
        if (tid < 256){
          unsigned long long k = kloc[0];
          if (kloc[1] > k) k = kloc[1];
          if (kloc[2] > k) k = kloc[2];
          if (kloc[3] > k) k = kloc[3];
          #pragma unroll
          for (int off=16; off; off>>=1){
            unsigned long long o = __shfl_xor_sync(0xffffffffu, k, off);
            if (o > k) k = o;
          }
          if (lane==0) warrk[wid] = k;
        }
        __syncthreads();
        if (tid==0){
          unsigned long long k = warrk[0];
          for (int w=1;w<8;w++) if (warrk[w] > k) k = warrk[w];
          chosen_k = k;
          idxs_s[round] = MM - (int)(unsigned)(k & 0xFFFFFFFFu);
        }
        __syncthreads();
        if (tid < 256){
          unsigned long long ck = chosen_k;
          #pragma unroll
          for (int z=0;z<4;z++) if (kloc[z]==ck) kloc[z] = 0ull;
        }
      }
      // parallel slot assignment (warp 0)
      if (tid < 32){
        bool valid = lane < TK;
        int row = idxs_s[valid ? lane : 0];
        int s = valid ? __ldcg(&g_slot[b2*MM + row]) : 0;
        unsigned nm = __ballot_sync(0xffffffffu, valid && s < 0);
        int cnt0 = 0;
        if (lane==0) cnt0 = __ldcg(&g_ovcnt[b2]);
        cnt0 = __shfl_sync(0xffffffffu, cnt0, 0);
        if (valid){
          int prev = s, slot = s;
          if (s < 0){
            slot = cnt0 + __popc(nm & ((1u<<lane)-1));
            __stcg(&g_slot[b2*MM + row], slot);
          }
          __stcg(&g_tk[b2*24 + lane*3 + 0], row);
          __stcg(&g_tk[b2*24 + lane*3 + 1], prev);
          __stcg(&g_tk[b2*24 + lane*3 + 2], slot);
        }
        if (lane==0) __stcg(&g_ovcnt[b2], cnt0 + __popc(nm));
      }
    }
    gbar(++bid);

    // ================= Phase C2 =================
    {
      const float4* h4g = (const float4*)g_h;
      float4* s4 = (float4*)sbuf;
      for (int i=tid;i<1024;i+=NT) s4[i] = __ldcg(&h4g[i]);
      if (t < SS-1){
        for (int i=tid;i<BB*TK*3;i+=NT) tk_s[i] = __ldcg(&g_tk[i]);
      }
      __syncthreads();
      // GEMV over all 512 threads: b = tid&15, jseg = tid>>4 (8 j each)
      {
        int b = tid&15, jseg = tid>>4;
        float a0=0.f, a1=0.f, a2=0.f, a3=0.f;
        #pragma unroll
        for (int jj=0;jj<8;jj++){
          int j = jseg*8 + jj;
          float hv = sbuf[j*16 + b];
          a0 = fmaf(wrow[j],        hv, a0);
          a1 = fmaf(wrow[256 + j],  hv, a1);
          a2 = fmaf(wrow[512 + j],  hv, a2);
          a3 = fmaf(wrow[768 + j],  hv, a3);
        }
        a0 += __shfl_xor_sync(0xffffffffu, a0, 16);
        a1 += __shfl_xor_sync(0xffffffffu, a1, 16);
        a2 += __shfl_xor_sync(0xffffffffu, a2, 16);
        a3 += __shfl_xor_sync(0xffffffffu, a3, 16);
        if ((tid&16)==0){
          cacc[b][0][wid]=a0; cacc[b][1][wid]=a1; cacc[b][2][wid]=a2; cacc[b][3][wid]=a3;
        }
      }
      __syncthreads();
      if (tid < 64){
        int b = tid&15, o = tid>>4;
        float s = 0.f;
        #pragma unroll
        for (int w=0;w<16;w++) s += cacc[b][o][w];
        float zi = zin_s[b];
        if (o < 2){
          out[((size_t)b*SS+t)*DD + dd0 + o] = s*zi + sbv[o];
        } else {
          int di = o-2;
          float gg = s*zi + scv[di] + __ldg(&g_gx[((size_t)t*BB+b)*DD + dd0 + di]);
          sgate[b][di] = 1.0f/(1.0f+expf(-gg));
        }
      }
      __syncthreads();
      if (t < SS-1 && tid < 256){
        int ent = tid>>1, di = tid&1;
        int b = ent>>3, i = ent&7;
        int row  = tk_s[(b*TK+i)*3 + 0];
        int prev = tk_s[(b*TK+i)*3 + 1];
        int slot = tk_s[(b*TK+i)*3 + 2];
        int d = dd0 + di;
        float old = (prev < 0) ? __ldg(&base[(size_t)row*DD + d])
                               : __ldcg(&g_ovl[((size_t)b*OV + prev)*DD + d]);
        float g = sgate[b][di];
        float xd = __ldg(&x[((size_t)b*SS+t)*DD + d]);
        __stcg(&g_ovl[((size_t)b*OV + slot)*DD + d], old + g*(xd - old));
      }
    }
    gbar(++bid);
  }
}

// =================== launch ===================
extern "C" void kernel_launch(void* const* d_in, const int* in_sizes, int n_in,
                              void* d_out, int out_size){
  const float* x      = (const float*)d_in[0];
  const float* memory = (const float*)d_in[1];
  const float* Wq     = (const float*)d_in[2];
  const float* bq     = (const float*)d_in[3];
  const float* Wk     = (const float*)d_in[4];
  // bk contributes only a softmax-invariant constant -> dropped
  const float* Wv     = (const float*)d_in[6];
  const float* bv     = (const float*)d_in[7];
  const float* Wu     = (const float*)d_in[8];
  const float* bu     = (const float*)d_in[9];
  float* out = (float*)d_out;

  static int attr_done = 0;
  if (!attr_done){
    cudaFuncSetAttribute(persist, cudaFuncAttributeMaxDynamicSharedMemorySize, 49152);
    attr_done = 1;
  }

  p_init1<<<NB, 256>>>(Wq, bq, Wk, Wv, bv, Wu);
  p_init2<<<NB, 256>>>(x, bu);
  persist<<<NB, NT, 49152>>>(memory, x, Wv, bv, out);
}

// round 14
// speedup vs baseline: 1.6862x; 1.0439x over previous
#include <cuda_runtime.h>
#include <math.h>
#include <float.h>

#define BB 16
#define SS 64
#define MM 2048
#define DD 256
#define TK 8
#define OV 512
#define NB 128
#define NT 512
#define SCALE 0.0625f

// ---- persistent state (no runtime allocs) ----
__device__ float g_ovl[BB*OV*DD];
__device__ int   g_slot[BB*MM];
__device__ int   g_ovcnt[BB];
__device__ __align__(16) float g_qk[SS*BB*DD];
__device__ __align__(16) float g_gx[SS*BB*DD];
__device__ float g_AT[DD*DD];
__device__ float g_avec[DD];
__device__ float g_WuT1[DD*DD];
__device__ float g_W2[DD*DD];
__device__ float g_cvec[DD];
__device__ __align__(16) float g_psum[BB*NB];      // [b][k]
__device__ __align__(16) float g_part[NB*DD*BB];   // [k][d][b]
__device__ __align__(16) float g_h[DD*BB];         // [j][b]
__device__ __align__(16) unsigned long long g_ck[NB*BB*TK];  // packed candidates
__device__ int   g_tk[BB*TK*3];
__device__ int   g_flag[NB*32];
__device__ int   g_gen2;

// =================== init launch 1 ===================
__global__ void p_init1(const float* __restrict__ Wq, const float* __restrict__ bq,
                        const float* __restrict__ Wk, const float* __restrict__ Wv,
                        const float* __restrict__ bv, const float* __restrict__ Wu){
  int blk = blockIdx.x, tid = threadIdx.x;
  if (blk < 32){
    int base = blk*2048;
    #pragma unroll
    for (int z=0;z<8;z++){ int e = base + z*256 + tid; int d = e>>8, j = e&255;
      g_WuT1[j*DD+d] = Wu[(size_t)d*2*DD + j]; }
  } else if (blk < 48){                // A tiles: g_AT[j][d]
    __shared__ float aq[16][68], ak[16][68];
    int tn = blk-32, j0 = (tn>>2)*64, d0 = (tn&3)*64;
    int ty = tid>>4, tx = tid&15;
    float acc[16];
    #pragma unroll
    for (int z=0;z<16;z++) acc[z]=0.f;
    for (int ib=0; ib<DD; ib+=16){
      #pragma unroll
      for (int z=0;z<4;z++){ int e = z*256+tid; int i=e>>6, j=e&63;
        aq[i][j] = Wq[(size_t)(ib+i)*DD + j0 + j];
        ak[i][j] = Wk[(size_t)(ib+i)*DD + d0 + j]; }
      __syncthreads();
      #pragma unroll
      for (int i=0;i<16;i++){
        float qv[4], kv[4];
        #pragma unroll
        for (int u=0;u<4;u++){ qv[u]=aq[i][ty*4+u]; kv[u]=ak[i][tx*4+u]; }
        #pragma unroll
        for (int jr=0;jr<4;jr++)
          #pragma unroll
          for (int dr=0;dr<4;dr++) acc[jr*4+dr] = fmaf(qv[jr], kv[dr], acc[jr*4+dr]);
      }
      __syncthreads();
    }
    #pragma unroll
    for (int jr=0;jr<4;jr++)
      #pragma unroll
      for (int dr=0;dr<4;dr++)
        g_AT[(size_t)(j0+ty*4+jr)*DD + d0+tx*4+dr] = acc[jr*4+dr]*SCALE;
  } else if (blk < 64){                // W2 tiles [d][i]
    __shared__ float wv[16][68], wu[16][68];
    int tn = blk-48, i0 = (tn>>2)*64, d0 = (tn&3)*64;
    int ty = tid>>4, tx = tid&15;
    float acc[16];
    #pragma unroll
    for (int z=0;z<16;z++) acc[z]=0.f;
    for (int jb=0; jb<DD; jb+=16){
      #pragma unroll
      for (int z=0;z<4;z++){ int e = z*256+tid; int jj=e>>6, ii=e&63;
        wv[jj][ii] = Wv[(size_t)(jb+jj)*DD + i0 + ii];
        wu[jj][ii] = Wu[(size_t)(d0+ii)*2*DD + DD + jb + jj]; }
      __syncthreads();
      #pragma unroll
      for (int jj=0;jj<16;jj++){
        float vv[4], uv[4];
        #pragma unroll
        for (int u=0;u<4;u++){ vv[u]=wv[jj][ty*4+u]; uv[u]=wu[jj][tx*4+u]; }
        #pragma unroll
        for (int ir=0;ir<4;ir++)
          #pragma unroll
          for (int dr=0;dr<4;dr++) acc[ir*4+dr] = fmaf(vv[ir], uv[dr], acc[ir*4+dr]);
      }
      __syncthreads();
    }
    #pragma unroll
    for (int ir=0;ir<4;ir++)
      #pragma unroll
      for (int dr=0;dr<4;dr++)
        g_W2[(size_t)(d0+tx*4+dr)*DD + i0+ty*4+ir] = acc[ir*4+dr];
  } else if (blk < 80){                // slot map clear
    int base = (blk-64)*2048;
    #pragma unroll
    for (int z=0;z<8;z++) g_slot[base + z*256 + tid] = -1;
  } else if (blk == 80){
    if (tid==0) g_gen2 = 0;
    if (tid < BB) g_ovcnt[tid] = 0;
    for (int i=tid;i<NB*32;i+=256) g_flag[i] = 0;
  } else if (blk == 81){               // avec
    __shared__ float bqs[DD];
    bqs[tid] = bq[tid]; __syncthreads();
    float acc = 0.f;
    #pragma unroll 4
    for (int i=0;i<DD;i++) acc = fmaf(Wk[(size_t)i*DD+tid], bqs[i], acc);
    g_avec[tid] = acc*SCALE;
  } else if (blk == 82){               // cvec
    __shared__ float bvs[DD];
    bvs[tid] = bv[tid]; __syncthreads();
    float acc = 0.f;
    #pragma unroll 4
    for (int j=0;j<DD;j++) acc = fmaf(Wu[(size_t)tid*2*DD + DD + j], bvs[j], acc);
    g_cvec[tid] = acc;
  }
}

// =================== init launch 2: qk / gx GEMMs ===================
__global__ void p_init2(const float* __restrict__ x, const float* __restrict__ bu){
  __shared__ float xt[64][17];
  __shared__ float wt[16][68];
  int blk = blockIdx.x, tid = threadIdx.x;
  int which = blk>>6;
  int r = blk&63;
  int s0 = (r>>2)*64, d0 = (r&3)*64;
  const float* W = which ? g_WuT1 : g_AT;
  int ty = tid>>4, tx = tid&15;
  float acc[16];
  #pragma unroll
  for (int z=0;z<16;z++) acc[z]=0.f;
  for (int jb=0; jb<DD; jb+=16){
    { int ss = tid>>2, jq = tid&3;
      float4 xv = *(const float4*)&x[(size_t)(s0+ss)*DD + jb + jq*4];
      xt[ss][jq*4+0]=xv.x; xt[ss][jq*4+1]=xv.y; xt[ss][jq*4+2]=xv.z; xt[ss][jq*4+3]=xv.w; }
    #pragma unroll
    for (int z=0;z<4;z++){ int e = z*256+tid; int jj=e>>6, dd=e&63;
      wt[jj][dd] = W[(size_t)(jb+jj)*DD + d0 + dd]; }
    __syncthreads();
    #pragma unroll
    for (int jj=0;jj<16;jj++){
      float xv[4], wv4[4];
      #pragma unroll
      for (int u=0;u<4;u++){ xv[u]=xt[ty*4+u][jj]; wv4[u]=wt[jj][tx*4+u]; }
      #pragma unroll
      for (int sr=0;sr<4;sr++)
        #pragma unroll
        for (int dr=0;dr<4;dr++) acc[sr*4+dr] = fmaf(xv[sr], wv4[dr], acc[sr*4+dr]);
    }
    __syncthreads();
  }
  float* dst = which ? g_gx : g_qk;
  const float* bias = which ? bu : g_avec;
  #pragma unroll
  for (int sr=0;sr<4;sr++){
    int s = s0 + ty*4 + sr;
    int b = s>>6, t = s&63;
    size_t ro = (size_t)(t*BB+b)*DD + d0 + tx*4;
    #pragma unroll
    for (int dr=0;dr<4;dr++) dst[ro+dr] = acc[sr*4+dr] + bias[d0+tx*4+dr];
  }
}

// =================== flag-array grid barrier (no atomics) ===================
__device__ __forceinline__ void gbar(int target){
  __syncthreads();
  int tid = threadIdx.x, blk = blockIdx.x;
  if (blk == 0){
    if (tid >= 1 && tid < NB){
      int v;
      do {
        asm volatile("ld.acquire.gpu.global.s32 %0, [%1];"
                     : "=r"(v) : "l"(&g_flag[tid*32]) : "memory");
      } while (v < target);
    }
    __syncthreads();
    if (tid == 0)
      asm volatile("st.release.gpu.global.s32 [%0], %1;"
                   :: "l"(&g_gen2), "r"(target) : "memory");
  } else {
    if (tid == 0){
      asm volatile("st.release.gpu.global.s32 [%0], %1;"
                   :: "l"(&g_flag[blk*32]), "r"(target) : "memory");
      int v;
      do {
        asm volatile("ld.acquire.gpu.global.s32 %0, [%1];"
                     : "=r"(v) : "l"(&g_gen2) : "memory");
      } while (v < target);
    }
    __syncthreads();
  }
}

__device__ __forceinline__ float dot4acc(float4 a, float4 b, float acc){
  acc = fmaf(a.x, b.x, acc);
  acc = fmaf(a.y, b.y, acc);
  acc = fmaf(a.z, b.z, acc);
  acc = fmaf(a.w, b.w, acc);
  return acc;
}

// =================== the persistent kernel (512 threads) ===================
__global__ void __launch_bounds__(NT, 1)
persist(const float* __restrict__ base, const float* __restrict__ x,
        const float* __restrict__ Wv, const float* __restrict__ bv,
        float* __restrict__ out){
  extern __shared__ float dsm[];
  float* rowsf = dsm;          // [16][256]
  float* qks   = dsm + 4096;   // [16][256]
  float* sbuf  = dsm + 8192;   // AB: spart[d][b] ; C2: h[j][b]

  __shared__ float sc[16][17];
  __shared__ __align__(16) float esm[16][16];   // [r][b]
  __shared__ int   dlist[256];
  __shared__ int   dcnt_s;
  __shared__ __align__(16) unsigned long long wtop[128];  // stage-1 merge outputs
  __shared__ __align__(16) float4 hred4[128];
  __shared__ __align__(16) float wrow[4*DD];
  __shared__ float cacc[16][4][17];
  __shared__ float sgate[16][2];
  __shared__ int   tk_s[BB*TK*3];
  __shared__ float zin_s[16];
  __shared__ float sbv[2], scv[2];

  int blk = blockIdx.x, tid = threadIdx.x;
  int m0 = blk*16;
  int wid = tid>>5, lane = tid&31;
  int dd0 = blk*2;

  // persistent smem loads
  for (int i=tid;i<16*DD;i+=NT) rowsf[i] = base[(size_t)m0*DD + i];
  {
    const float4* q4 = (const float4*)g_qk;
    float4* qd = (float4*)qks;
    for (int i=tid;i<1024;i+=NT) qd[i] = __ldg(&q4[i]);
  }
  { int i = tid; if (i < 2*DD){ wrow[i] = Wv[(size_t)dd0*DD + i]; wrow[2*DD+i] = g_W2[(size_t)dd0*DD + i]; } }
  if (tid<2){ sbv[tid] = bv[dd0+tid]; scv[tid] = g_cvec[dd0+tid]; }
  __syncthreads();

  // ---- loop-invariant register caches ----
  // score GEMM base rows: warp owns rows r0..r0+3, lane's 8 j's
  int sg_bq0 = (wid&3)*4, sg_r0 = (wid>>2)*4, sg_j0 = lane*8;
  float4 ra_c[8];
  #pragma unroll
  for (int hh=0; hh<2; hh++)
    #pragma unroll
    for (int u=0;u<4;u++)
      ra_c[hh*4+u] = *(const float4*)&rowsf[(sg_r0+u)*256 + sg_j0 + hh*4];

  int bid = 0;
  for (int t=0;t<SS;t++){
    // ================= Phase AB =================
    if (tid==0) dcnt_s = 0;
    __syncthreads();
    if (tid < 256){
      int b = tid>>4, r = tid&15;
      int s = __ldcg(&g_slot[b*MM + m0 + r]);
      if (s >= 0){ int p = atomicAdd(&dcnt_s,1); dlist[p] = (b<<16)|(r<<12)|s; }
    }
    // score GEMM: 4x4 tile/warp, lane splits K; ra from registers
    {
      float acc[16];
      #pragma unroll
      for (int z=0;z<16;z++) acc[z]=0.f;
      #pragma unroll
      for (int hh=0; hh<2; hh++){
        int jb = sg_j0 + hh*4;
        float4 qa[4];
        #pragma unroll
        for (int u=0;u<4;u++) qa[u] = *(const float4*)&qks[(sg_bq0+u)*256 + jb];
        #pragma unroll
        for (int bi=0;bi<4;bi++)
          #pragma unroll
          for (int ri=0;ri<4;ri++)
            acc[bi*4+ri] = dot4acc(qa[bi], ra_c[hh*4+ri], acc[bi*4+ri]);
      }
      // reduce-and-swap butterfly: 16 SHFL total
      {
        bool hi = (lane & 16);
        #pragma unroll
        for (int z=0;z<8;z++){
          float send = hi ? acc[z] : acc[z+8];
          float r = __shfl_xor_sync(0xffffffffu, send, 16);
          acc[z] = (hi ? acc[z+8] : acc[z]) + r;
        }
      }
      {
        bool hi = (lane & 8);
        #pragma unroll
        for (int z=0;z<4;z++){
          float send = hi ? acc[z] : acc[z+4];
          float r = __shfl_xor_sync(0xffffffffu, send, 8);
          acc[z] = (hi ? acc[z+4] : acc[z]) + r;
        }
      }
      {
        bool hi = (lane & 4);
        #pragma unroll
        for (int z=0;z<2;z++){
          float send = hi ? acc[z] : acc[z+2];
          float r = __shfl_xor_sync(0xffffffffu, send, 4);
          acc[z] = (hi ? acc[z+2] : acc[z]) + r;
        }
      }
      {
        bool hi = (lane & 2);
        float send = hi ? acc[0] : acc[1];
        float r = __shfl_xor_sync(0xffffffffu, send, 2);
        acc[0] = (hi ? acc[1] : acc[0]) + r;
      }
      acc[0] += __shfl_xor_sync(0xffffffffu, acc[0], 1);
      if ((lane & 1) == 0){
        int z = (lane>>1) & 15;
        sc[sg_bq0 + (z>>2)][sg_r0 + (z&3)] = acc[0];
      }
    }
    __syncthreads();
    int dn = dcnt_s;
    // dirty score fixes (16 warps over entries)
    for (int e=wid; e<dn; e+=16){
      int pk = dlist[e]; int eb = pk>>16, er = (pk>>12)&15, es = pk&0xfff;
      const float* ov = g_ovl + ((size_t)eb*OV + es)*DD;
      float a2 = 0.f;
      #pragma unroll
      for (int k=0;k<8;k++) a2 = fmaf(__ldcg(&ov[lane+32*k]), qks[eb*256 + lane+32*k], a2);
      #pragma unroll
      for (int off=16; off; off>>=1) a2 += __shfl_xor_sync(0xffffffffu, a2, off);
      if (lane==0) sc[eb][er] = a2;
    }
    __syncthreads();
    // exp + psum (warps 0-7) ; candidate bitonic top-8 (warps 8-15)
    if (tid < 256){
      int b = tid>>4, r = tid&15;
      float e = expf(sc[b][r]);
      esm[r][b] = e;
      float ps = e;
      #pragma unroll
      for (int off=8; off; off>>=1) ps += __shfl_xor_sync(0xffffffffu, ps, off);
      if (r==0) __stcg(&g_psum[b*NB + blk], ps);
    } else if (t < SS-1){
      int w2 = wid - 8;
      int hw = lane>>4, l4 = lane&15;
      int b = w2*2 + hw;
      float v = sc[b][l4];
      unsigned u = __float_as_uint(v);
      u = (u & 0x80000000u) ? ~u : (u | 0x80000000u);
      unsigned long long key = ((unsigned long long)u << 32) | (unsigned)(MM - (m0 + l4));
      #pragma unroll
      for (int k2=2; k2<=16; k2<<=1){
        #pragma unroll
        for (int j=k2>>1; j>0; j>>=1){
          unsigned long long o = __shfl_xor_sync(0xffffffffu, key, j);
          bool keep_max = ((l4 & k2)==0) == ((l4 & j)==0);
          key = keep_max ? (key > o ? key : o) : (key < o ? key : o);
        }
      }
      if (l4 < 8) __stcg(&g_ck[(size_t)(blk*BB+b)*TK + l4], key);
    }
    __syncthreads();
    // base partials: 2 threads per d
    {
      int d = tid>>1, half = tid&1;
      float4 A0 = make_float4(0.f,0.f,0.f,0.f), A1 = A0;
      #pragma unroll
      for (int r=0;r<16;r++){
        float4 e0 = *(const float4*)&esm[r][half*8];
        float4 e1 = *(const float4*)&esm[r][half*8+4];
        float rr = rowsf[r*256 + d];
        A0.x = fmaf(e0.x, rr, A0.x); A0.y = fmaf(e0.y, rr, A0.y);
        A0.z = fmaf(e0.z, rr, A0.z); A0.w = fmaf(e0.w, rr, A0.w);
        A1.x = fmaf(e1.x, rr, A1.x); A1.y = fmaf(e1.y, rr, A1.y);
        A1.z = fmaf(e1.z, rr, A1.z); A1.w = fmaf(e1.w, rr, A1.w);
      }
      *(float4*)&sbuf[d*16 + half*8]     = A0;
      *(float4*)&sbuf[d*16 + half*8 + 4] = A1;
    }
    __syncthreads();
    // dirty partial corrections: warp w owns batch eb==w
    {
      float corr[8] = {0.f,0.f,0.f,0.f,0.f,0.f,0.f,0.f};
      bool any = false;
      for (int e=0;e<dn;e++){
        int pk = dlist[e];
        if ((pk>>16) == wid){
          int er = (pk>>12)&15, es = pk&0xfff;
          float ev = esm[er][wid];
          const float* ov = g_ovl + ((size_t)wid*OV + es)*DD;
          any = true;
          #pragma unroll
          for (int k=0;k<8;k++){
            int d = lane+32*k;
            corr[k] = fmaf(ev, __ldcg(&ov[d]) - rowsf[er*256 + d], corr[k]);
          }
        }
      }
      if (any){
        #pragma unroll
        for (int k=0;k<8;k++){ int d = lane+32*k; sbuf[d*16 + wid] += corr[k]; }
      }
    }
    __syncthreads();
    // store partials [k][d][b]
    {
      int d = tid>>1, half = tid&1;
      float4* gp4 = (float4*)g_part;
      __stcg(&gp4[((size_t)blk*256 + d)*4 + half*2 + 0], *(const float4*)&sbuf[d*16 + half*8]);
      __stcg(&gp4[((size_t)blk*256 + d)*4 + half*2 + 1], *(const float4*)&sbuf[d*16 + half*8 + 4]);
    }
    gbar(++bid);

    // ================= Phase C1 =================
    // h reduce for this block's d-chunk
    {
      const float4* gp4 = (const float4*)g_part;
      int q = tid&7, kg = tid>>3;
      float4 a4 = __ldcg(&gp4[((size_t)kg*256 + dd0 + (q>>2))*4 + (q&3)]);
      float4 b4 = __ldcg(&gp4[((size_t)(kg+64)*256 + dd0 + (q>>2))*4 + (q&3)]);
      a4.x += b4.x; a4.y += b4.y; a4.z += b4.z; a4.w += b4.w;
      #pragma unroll
      for (int off=8; off<=16; off<<=1){
        a4.x += __shfl_xor_sync(0xffffffffu, a4.x, off);
        a4.y += __shfl_xor_sync(0xffffffffu, a4.y, off);
        a4.z += __shfl_xor_sync(0xffffffffu, a4.z, off);
        a4.w += __shfl_xor_sync(0xffffffffu, a4.w, off);
      }
      if (lane < 8) hred4[wid*8 + lane] = a4;
      __syncthreads();
      if (tid < 64){ float4 u=hred4[tid], v=hred4[tid+64];
        u.x+=v.x; u.y+=v.y; u.z+=v.z; u.w+=v.w; hred4[tid]=u; }
      __syncthreads();
      if (tid < 32){ float4 u=hred4[tid], v=hred4[tid+32];
        u.x+=v.x; u.y+=v.y; u.z+=v.z; u.w+=v.w; hred4[tid]=u; }
      __syncthreads();
      if (tid < 16){ float4 u=hred4[tid], v=hred4[tid+16];
        u.x+=v.x; u.y+=v.y; u.z+=v.z; u.w+=v.w; hred4[tid]=u; }
      __syncthreads();
      if (tid < 8){ float4 u=hred4[tid], v=hred4[tid+8];
        u.x+=v.x; u.y+=v.y; u.z+=v.z; u.w+=v.w;
        __stcg(&((float4*)g_h)[dd0*4 + tid], u); }
    }
    // local 1/Z for all 16 batches
    {
      const float4* ps4 = (const float4*)&g_psum[wid*NB];
      float4 p4 = __ldcg(&ps4[lane]);
      float zp = (p4.x+p4.y)+(p4.z+p4.w);
      #pragma unroll
      for (int off=16; off; off>>=1) zp += __shfl_xor_sync(0xffffffffu, zp, off);
      if (lane==0) zin_s[wid] = 1.0f/zp;
    }
    if (t+1 < SS){
      const float4* q4 = (const float4*)(g_qk + (size_t)(t+1)*BB*DD);
      float4* qd = (float4*)qks;
      for (int i=tid;i<1024;i+=NT) qd[i] = __ldg(&q4[i]);
    }
    if (blk < BB && t < SS-1){
      int b2 = blk;
      // ---- stage 1: 16 warps x 64 candidates -> per-warp top-8 (warp-local) ----
      {
        int kk = wid*32 + lane;   // chunk pair index: covers 2 chunks per lane? no:
        // each warp handles candidate range [wid*64, wid*64+64): 2 keys/lane
        unsigned long long k0, k1;
        {
          int c0 = wid*64 + lane;          // candidate index 0
          int c1 = wid*64 + 32 + lane;     // candidate index 1
          k0 = __ldcg(&g_ck[(size_t)((c0>>3)*BB + b2)*TK + (c0&7)]);
          k1 = __ldcg(&g_ck[(size_t)((c1>>3)*BB + b2)*TK + (c1&7)]);
        }
        (void)kk;
        #pragma unroll
        for (int round=0; round<TK; round++){
          unsigned long long k = k0 > k1 ? k0 : k1;
          #pragma unroll
          for (int off=16; off; off>>=1){
            unsigned long long o = __shfl_xor_sync(0xffffffffu, k, off);
            if (o > k) k = o;
          }
          if (lane == round) wtop[wid*8 + round] = k;
          if (k0 == k) k0 = 0ull;
          if (k1 == k) k1 = 0ull;
        }
      }
      __syncthreads();
      // ---- stage 2: warp 0 merges 128 keys (4/lane), keeps round-i row in lane i ----
      if (wid == 0){
        unsigned long long kl[4];
        kl[0] = wtop[lane]; kl[1] = wtop[lane+32];
        kl[2] = wtop[lane+64]; kl[3] = wtop[lane+96];
        int myrow = 0;
        #pragma unroll
        for (int round=0; round<TK; round++){
          unsigned long long k = kl[0];
          if (kl[1] > k) k = kl[1];
          if (kl[2] > k) k = kl[2];
          if (kl[3] > k) k = kl[3];
          #pragma unroll
          for (int off=16; off; off>>=1){
            unsigned long long o = __shfl_xor_sync(0xffffffffu, k, off);
            if (o > k) k = o;
          }
          if (lane == round) myrow = MM - (int)(unsigned)(k & 0xFFFFFFFFu);
          #pragma unroll
          for (int z=0;z<4;z++) if (kl[z]==k) kl[z] = 0ull;
        }
        // slot assignment (warp-local ballot)
        bool valid = lane < TK;
        int row = valid ? myrow : 0;
        int s = valid ? __ldcg(&g_slot[b2*MM + row]) : 0;
        unsigned nm = __ballot_sync(0xffffffffu, valid && s < 0);
        int cnt0 = 0;
        if (lane==0) cnt0 = __ldcg(&g_ovcnt[b2]);
        cnt0 = __shfl_sync(0xffffffffu, cnt0, 0);
        if (valid){
          int prev = s, slot = s;
          if (s < 0){
            slot = cnt0 + __popc(nm & ((1u<<lane)-1));
            __stcg(&g_slot[b2*MM + row], slot);
          }
          __stcg(&g_tk[b2*24 + lane*3 + 0], row);
          __stcg(&g_tk[b2*24 + lane*3 + 1], prev);
          __stcg(&g_tk[b2*24 + lane*3 + 2], slot);
        }
        if (lane==0) __stcg(&g_ovcnt[b2], cnt0 + __popc(nm));
      }
    }
    gbar(++bid);

    // ================= Phase C2 =================
    {
      const float4* h4g = (const float4*)g_h;
      float4* s4 = (float4*)sbuf;
      for (int i=tid;i<1024;i+=NT) s4[i] = __ldcg(&h4g[i]);
      if (t < SS-1){
        for (int i=tid;i<BB*TK*3;i+=NT) tk_s[i] = __ldcg(&g_tk[i]);
      }
      __syncthreads();
      // GEMV over all 512 threads
      {
        int b = tid&15, jseg = tid>>4;
        float a0=0.f, a1=0.f, a2=0.f, a3=0.f;
        #pragma unroll
        for (int jj=0;jj<8;jj++){
          int j = jseg*8 + jj;
          float hv = sbuf[j*16 + b];
          a0 = fmaf(wrow[j],        hv, a0);
          a1 = fmaf(wrow[256 + j],  hv, a1);
          a2 = fmaf(wrow[512 + j],  hv, a2);
          a3 = fmaf(wrow[768 + j],  hv, a3);
        }
        a0 += __shfl_xor_sync(0xffffffffu, a0, 16);
        a1 += __shfl_xor_sync(0xffffffffu, a1, 16);
        a2 += __shfl_xor_sync(0xffffffffu, a2, 16);
        a3 += __shfl_xor_sync(0xffffffffu, a3, 16);
        if ((tid&16)==0){
          cacc[b][0][wid]=a0; cacc[b][1][wid]=a1; cacc[b][2][wid]=a2; cacc[b][3][wid]=a3;
        }
      }
      __syncthreads();
      if (tid < 64){
        int b = tid&15, o = tid>>4;
        float s = 0.f;
        #pragma unroll
        for (int w=0;w<16;w++) s += cacc[b][o][w];
        float zi = zin_s[b];
        if (o < 2){
          out[((size_t)b*SS+t)*DD + dd0 + o] = s*zi + sbv[o];
        } else {
          int di = o-2;
          float gg = s*zi + scv[di] + __ldg(&g_gx[((size_t)t*BB+b)*DD + dd0 + di]);
          sgate[b][di] = 1.0f/(1.0f+expf(-gg));
        }
      }
      __syncthreads();
      if (t < SS-1 && tid < 256){
        int ent = tid>>1, di = tid&1;
        int b = ent>>3, i = ent&7;
        int row  = tk_s[(b*TK+i)*3 + 0];
        int prev = tk_s[(b*TK+i)*3 + 1];
        int slot = tk_s[(b*TK+i)*3 + 2];
        int d = dd0 + di;
        float old = (prev < 0) ? __ldg(&base[(size_t)row*DD + d])
                               : __ldcg(&g_ovl[((size_t)b*OV + prev)*DD + d]);
        float g = sgate[b][di];
        float xd = __ldg(&x[((size_t)b*SS+t)*DD + d]);
        __stcg(&g_ovl[((size_t)b*OV + slot)*DD + d], old + g*(xd - old));
      }
    }
    gbar(++bid);
  }
}

// =================== launch ===================
extern "C" void kernel_launch(void* const* d_in, const int* in_sizes, int n_in,
                              void* d_out, int out_size){
  const float* x      = (const float*)d_in[0];
  const float* memory = (const float*)d_in[1];
  const float* Wq     = (const float*)d_in[2];
  const float* bq     = (const float*)d_in[3];
  const float* Wk     = (const float*)d_in[4];
  // bk contributes only a softmax-invariant constant -> dropped
  const float* Wv     = (const float*)d_in[6];
  const float* bv     = (const float*)d_in[7];
  const float* Wu     = (const float*)d_in[8];
  const float* bu     = (const float*)d_in[9];
  float* out = (float*)d_out;

  static int attr_done = 0;
  if (!attr_done){
    cudaFuncSetAttribute(persist, cudaFuncAttributeMaxDynamicSharedMemorySize, 49152);
    attr_done = 1;
  }

  p_init1<<<NB, 256>>>(Wq, bq, Wk, Wv, bv, Wu);
  p_init2<<<NB, 256>>>(x, bu);
  persist<<<NB, NT, 49152>>>(memory, x, Wv, bv, out);
}

// round 15
// speedup vs baseline: 1.6891x; 1.0017x over previous
#include <cuda_runtime.h>
#include <math.h>
#include <float.h>

#define BB 16
#define SS 64
#define MM 2048
#define DD 256
#define TK 8
#define OV 512
#define NB 128
#define NT 512
#define SCALE 0.0625f

typedef unsigned long long ull;

// ---- persistent state (no runtime allocs) ----
__device__ float g_ovl[BB*OV*DD];
__device__ int   g_slot[BB*MM];
__device__ int   g_ovcnt[BB];
__device__ __align__(16) float g_qk[SS*BB*DD];
__device__ __align__(16) float g_gx[SS*BB*DD];
__device__ float g_AT[DD*DD];
__device__ float g_avec[DD];
__device__ float g_WuT1[DD*DD];
__device__ float g_W2[DD*DD];
__device__ float g_cvec[DD];
__device__ __align__(16) float g_psum[BB*NB];      // [b][k]
__device__ __align__(16) float g_part[NB*DD*BB];   // [k][d][b]
__device__ __align__(16) float g_h[DD*BB];         // [j][b]
__device__ __align__(16) ull   g_ck[NB*BB*TK];     // packed candidates
__device__ int   g_tk[BB*TK*3];
__device__ int   g_flag[NB*32];
__device__ int   g_gen2;

// =================== init launch 1 ===================
__global__ void p_init1(const float* __restrict__ Wq, const float* __restrict__ bq,
                        const float* __restrict__ Wk, const float* __restrict__ Wv,
                        const float* __restrict__ bv, const float* __restrict__ Wu){
  int blk = blockIdx.x, tid = threadIdx.x;
  if (blk < 32){
    int base = blk*2048;
    #pragma unroll
    for (int z=0;z<8;z++){ int e = base + z*256 + tid; int d = e>>8, j = e&255;
      g_WuT1[j*DD+d] = Wu[(size_t)d*2*DD + j]; }
  } else if (blk < 48){                // A tiles: g_AT[j][d]
    __shared__ float aq[16][68], ak[16][68];
    int tn = blk-32, j0 = (tn>>2)*64, d0 = (tn&3)*64;
    int ty = tid>>4, tx = tid&15;
    float acc[16];
    #pragma unroll
    for (int z=0;z<16;z++) acc[z]=0.f;
    for (int ib=0; ib<DD; ib+=16){
      #pragma unroll
      for (int z=0;z<4;z++){ int e = z*256+tid; int i=e>>6, j=e&63;
        aq[i][j] = Wq[(size_t)(ib+i)*DD + j0 + j];
        ak[i][j] = Wk[(size_t)(ib+i)*DD + d0 + j]; }
      __syncthreads();
      #pragma unroll
      for (int i=0;i<16;i++){
        float qv[4], kv[4];
        #pragma unroll
        for (int u=0;u<4;u++){ qv[u]=aq[i][ty*4+u]; kv[u]=ak[i][tx*4+u]; }
        #pragma unroll
        for (int jr=0;jr<4;jr++)
          #pragma unroll
          for (int dr=0;dr<4;dr++) acc[jr*4+dr] = fmaf(qv[jr], kv[dr], acc[jr*4+dr]);
      }
      __syncthreads();
    }
    #pragma unroll
    for (int jr=0;jr<4;jr++)
      #pragma unroll
      for (int dr=0;dr<4;dr++)
        g_AT[(size_t)(j0+ty*4+jr)*DD + d0+tx*4+dr] = acc[jr*4+dr]*SCALE;
  } else if (blk < 64){                // W2 tiles [d][i]
    __shared__ float wv[16][68], wu[16][68];
    int tn = blk-48, i0 = (tn>>2)*64, d0 = (tn&3)*64;
    int ty = tid>>4, tx = tid&15;
    float acc[16];
    #pragma unroll
    for (int z=0;z<16;z++) acc[z]=0.f;
    for (int jb=0; jb<DD; jb+=16){
      #pragma unroll
      for (int z=0;z<4;z++){ int e = z*256+tid; int jj=e>>6, ii=e&63;
        wv[jj][ii] = Wv[(size_t)(jb+jj)*DD + i0 + ii];
        wu[jj][ii] = Wu[(size_t)(d0+ii)*2*DD + DD + jb + jj]; }
      __syncthreads();
      #pragma unroll
      for (int jj=0;jj<16;jj++){
        float vv[4], uv[4];
        #pragma unroll
        for (int u=0;u<4;u++){ vv[u]=wv[jj][ty*4+u]; uv[u]=wu[jj][tx*4+u]; }
        #pragma unroll
        for (int ir=0;ir<4;ir++)
          #pragma unroll
          for (int dr=0;dr<4;dr++) acc[ir*4+dr] = fmaf(vv[ir], uv[dr], acc[ir*4+dr]);
      }
      __syncthreads();
    }
    #pragma unroll
    for (int ir=0;ir<4;ir++)
      #pragma unroll
      for (int dr=0;dr<4;dr++)
        g_W2[(size_t)(d0+tx*4+dr)*DD + i0+ty*4+ir] = acc[ir*4+dr];
  } else if (blk < 80){                // slot map clear
    int base = (blk-64)*2048;
    #pragma unroll
    for (int z=0;z<8;z++) g_slot[base + z*256 + tid] = -1;
  } else if (blk == 80){
    if (tid==0) g_gen2 = 0;
    if (tid < BB) g_ovcnt[tid] = 0;
    for (int i=tid;i<NB*32;i+=256) g_flag[i] = 0;
  } else if (blk == 81){               // avec
    __shared__ float bqs[DD];
    bqs[tid] = bq[tid]; __syncthreads();
    float acc = 0.f;
    #pragma unroll 4
    for (int i=0;i<DD;i++) acc = fmaf(Wk[(size_t)i*DD+tid], bqs[i], acc);
    g_avec[tid] = acc*SCALE;
  } else if (blk == 82){               // cvec
    __shared__ float bvs[DD];
    bvs[tid] = bv[tid]; __syncthreads();
    float acc = 0.f;
    #pragma unroll 4
    for (int j=0;j<DD;j++) acc = fmaf(Wu[(size_t)tid*2*DD + DD + j], bvs[j], acc);
    g_cvec[tid] = acc;
  }
}

// =================== init launch 2: qk / gx GEMMs ===================
__global__ void p_init2(const float* __restrict__ x, const float* __restrict__ bu){
  __shared__ float xt[64][17];
  __shared__ float wt[16][68];
  int blk = blockIdx.x, tid = threadIdx.x;
  int which = blk>>6;
  int r = blk&63;
  int s0 = (r>>2)*64, d0 = (r&3)*64;
  const float* W = which ? g_WuT1 : g_AT;
  int ty = tid>>4, tx = tid&15;
  float acc[16];
  #pragma unroll
  for (int z=0;z<16;z++) acc[z]=0.f;
  for (int jb=0; jb<DD; jb+=16){
    { int ss = tid>>2, jq = tid&3;
      float4 xv = *(const float4*)&x[(size_t)(s0+ss)*DD + jb + jq*4];
      xt[ss][jq*4+0]=xv.x; xt[ss][jq*4+1]=xv.y; xt[ss][jq*4+2]=xv.z; xt[ss][jq*4+3]=xv.w; }
    #pragma unroll
    for (int z=0;z<4;z++){ int e = z*256+tid; int jj=e>>6, dd=e&63;
      wt[jj][dd] = W[(size_t)(jb+jj)*DD + d0 + dd]; }
    __syncthreads();
    #pragma unroll
    for (int jj=0;jj<16;jj++){
      float xv[4], wv4[4];
      #pragma unroll
      for (int u=0;u<4;u++){ xv[u]=xt[ty*4+u][jj]; wv4[u]=wt[jj][tx*4+u]; }
      #pragma unroll
      for (int sr=0;sr<4;sr++)
        #pragma unroll
        for (int dr=0;dr<4;dr++) acc[sr*4+dr] = fmaf(xv[sr], wv4[dr], acc[sr*4+dr]);
    }
    __syncthreads();
  }
  float* dst = which ? g_gx : g_qk;
  const float* bias = which ? bu : g_avec;
  #pragma unroll
  for (int sr=0;sr<4;sr++){
    int s = s0 + ty*4 + sr;
    int b = s>>6, t = s&63;
    size_t ro = (size_t)(t*BB+b)*DD + d0 + tx*4;
    #pragma unroll
    for (int dr=0;dr<4;dr++) dst[ro+dr] = acc[sr*4+dr] + bias[d0+tx*4+dr];
  }
}

// =================== flag-array grid barrier (no atomics) ===================
__device__ __forceinline__ void gbar(int target){
  __syncthreads();
  int tid = threadIdx.x, blk = blockIdx.x;
  if (blk == 0){
    if (tid >= 1 && tid < NB){
      int v;
      do {
        asm volatile("ld.acquire.gpu.global.s32 %0, [%1];"
                     : "=r"(v) : "l"(&g_flag[tid*32]) : "memory");
      } while (v < target);
    }
    __syncthreads();
    if (tid == 0)
      asm volatile("st.release.gpu.global.s32 [%0], %1;"
                   :: "l"(&g_gen2), "r"(target) : "memory");
  } else {
    if (tid == 0){
      asm volatile("st.release.gpu.global.s32 [%0], %1;"
                   :: "l"(&g_flag[blk*32]), "r"(target) : "memory");
      int v;
      do {
        asm volatile("ld.acquire.gpu.global.s32 %0, [%1];"
                     : "=r"(v) : "l"(&g_gen2) : "memory");
      } while (v < target);
    }
    __syncthreads();
  }
}

// ---- packed f32x2 helpers ----
__device__ __forceinline__ void fma2(ull &d, ull a, ull b){
  asm("fma.rn.f32x2 %0, %1, %2, %0;" : "+l"(d) : "l"(a), "l"(b));
}
__device__ __forceinline__ ull pk2(float lo, float hi){
  ull r; asm("mov.b64 %0, {%1, %2};" : "=l"(r) : "f"(lo), "f"(hi)); return r;
}
__device__ __forceinline__ float upk_sum(ull v){
  float lo, hi; asm("mov.b64 {%0, %1}, %2;" : "=f"(lo), "=f"(hi) : "l"(v));
  return lo + hi;
}
__device__ __forceinline__ float upk_sel(ull v, int hi_sel){
  float lo, hi; asm("mov.b64 {%0, %1}, %2;" : "=f"(lo), "=f"(hi) : "l"(v));
  return hi_sel ? hi : lo;
}

// =================== the persistent kernel (512 threads) ===================
__global__ void __launch_bounds__(NT, 1)
persist(const float* __restrict__ base, const float* __restrict__ x,
        const float* __restrict__ Wv, const float* __restrict__ bv,
        float* __restrict__ out){
  extern __shared__ float dsm[];
  float* rowsf = dsm;          // [16][256]
  float* qks   = dsm + 4096;   // [16][256]
  float* sbuf  = dsm + 8192;   // AB: spart[d][b] ; C2: h[j][b]

  __shared__ float sc[16][17];
  __shared__ __align__(16) ull esm2[128];       // [rp][b] packed (e[2rp],e[2rp+1])
  __shared__ int   dlist[256];
  __shared__ int   dcnt_s;
  __shared__ __align__(16) ull wtop[128];
  __shared__ __align__(16) float4 hred4[128];
  __shared__ __align__(16) float wrow[4*DD];
  __shared__ float cacc[16][4][17];
  __shared__ float sgate[16][2];
  __shared__ int   tk_s[BB*TK*3];
  __shared__ float zin_s[16];
  __shared__ float sbv[2], scv[2];

  int blk = blockIdx.x, tid = threadIdx.x;
  int m0 = blk*16;
  int wid = tid>>5, lane = tid&31;
  int dd0 = blk*2;

  // persistent smem loads
  for (int i=tid;i<16*DD;i+=NT) rowsf[i] = base[(size_t)m0*DD + i];
  {
    const float4* q4 = (const float4*)g_qk;
    float4* qd = (float4*)qks;
    for (int i=tid;i<1024;i+=NT) qd[i] = __ldg(&q4[i]);
  }
  { int i = tid; if (i < 2*DD){ wrow[i] = Wv[(size_t)dd0*DD + i]; wrow[2*DD+i] = g_W2[(size_t)dd0*DD + i]; } }
  if (tid<2){ sbv[tid] = bv[dd0+tid]; scv[tid] = g_cvec[dd0+tid]; }
  __syncthreads();

  // ---- loop-invariant register cache: score GEMM base rows ----
  int sg_bq0 = (wid&3)*4, sg_r0 = (wid>>2)*4, sg_j0 = lane*8;
  float4 ra_c[8];
  #pragma unroll
  for (int hh=0; hh<2; hh++)
    #pragma unroll
    for (int u=0;u<4;u++)
      ra_c[hh*4+u] = *(const float4*)&rowsf[(sg_r0+u)*256 + sg_j0 + hh*4];

  int bid = 0;
  for (int t=0;t<SS;t++){
    // ================= Phase AB =================
    if (tid==0) dcnt_s = 0;
    __syncthreads();
    if (tid < 256){
      int b = tid>>4, r = tid&15;
      int s = __ldcg(&g_slot[b*MM + m0 + r]);
      if (s >= 0){ int p = atomicAdd(&dcnt_s,1); dlist[p] = (b<<16)|(r<<12)|s; }
    }
    // score GEMM: 4x4 tile/warp, lane splits K; j-paired fma.f32x2
    {
      ull acc2[16];
      #pragma unroll
      for (int z=0;z<16;z++) acc2[z]=0ull;
      #pragma unroll
      for (int hh=0; hh<2; hh++){
        int jb = sg_j0 + hh*4;
        ulonglong2 qa2[4];
        #pragma unroll
        for (int u=0;u<4;u++) qa2[u] = *(const ulonglong2*)&qks[(sg_bq0+u)*256 + jb];
        #pragma unroll
        for (int bi=0;bi<4;bi++)
          #pragma unroll
          for (int ri=0;ri<4;ri++){
            ulonglong2 rr = *(const ulonglong2*)&ra_c[hh*4+ri];
            fma2(acc2[bi*4+ri], qa2[bi].x, rr.x);
            fma2(acc2[bi*4+ri], qa2[bi].y, rr.y);
          }
      }
      float acc[16];
      #pragma unroll
      for (int z=0;z<16;z++) acc[z] = upk_sum(acc2[z]);
      // reduce-and-swap butterfly: 16 SHFL total
      {
        bool hi = (lane & 16);
        #pragma unroll
        for (int z=0;z<8;z++){
          float send = hi ? acc[z] : acc[z+8];
          float r = __shfl_xor_sync(0xffffffffu, send, 16);
          acc[z] = (hi ? acc[z+8] : acc[z]) + r;
        }
      }
      {
        bool hi = (lane & 8);
        #pragma unroll
        for (int z=0;z<4;z++){
          float send = hi ? acc[z] : acc[z+4];
          float r = __shfl_xor_sync(0xffffffffu, send, 8);
          acc[z] = (hi ? acc[z+4] : acc[z]) + r;
        }
      }
      {
        bool hi = (lane & 4);
        #pragma unroll
        for (int z=0;z<2;z++){
          float send = hi ? acc[z] : acc[z+2];
          float r = __shfl_xor_sync(0xffffffffu, send, 4);
          acc[z] = (hi ? acc[z+2] : acc[z]) + r;
        }
      }
      {
        bool hi = (lane & 2);
        float send = hi ? acc[0] : acc[1];
        float r = __shfl_xor_sync(0xffffffffu, send, 2);
        acc[0] = (hi ? acc[1] : acc[0]) + r;
      }
      acc[0] += __shfl_xor_sync(0xffffffffu, acc[0], 1);
      if ((lane & 1) == 0){
        int z = (lane>>1) & 15;
        sc[sg_bq0 + (z>>2)][sg_r0 + (z&3)] = acc[0];
      }
    }
    __syncthreads();
    int dn = dcnt_s;
    // dirty score fixes (16 warps over entries)
    for (int e=wid; e<dn; e+=16){
      int pk = dlist[e]; int eb = pk>>16, er = (pk>>12)&15, es = pk&0xfff;
      const float* ov = g_ovl + ((size_t)eb*OV + es)*DD;
      float a2 = 0.f;
      #pragma unroll
      for (int k=0;k<8;k++) a2 = fmaf(__ldcg(&ov[lane+32*k]), qks[eb*256 + lane+32*k], a2);
      #pragma unroll
      for (int off=16; off; off>>=1) a2 += __shfl_xor_sync(0xffffffffu, a2, off);
      if (lane==0) sc[eb][er] = a2;
    }
    __syncthreads();
    // exp + psum + packed-pair store (warps 0-7) ; candidate bitonic top-8 (warps 8-15)
    if (tid < 256){
      int b = tid>>4, r = tid&15;
      float e = expf(sc[b][r]);
      float eo = __shfl_down_sync(0xffffffffu, e, 1);
      if ((r & 1) == 0) esm2[(r>>1)*16 + b] = pk2(e, eo);
      float ps = e;
      #pragma unroll
      for (int off=8; off; off>>=1) ps += __shfl_xor_sync(0xffffffffu, ps, off);
      if (r==0) __stcg(&g_psum[b*NB + blk], ps);
    } else if (t < SS-1){
      int w2 = wid - 8;
      int hw = lane>>4, l4 = lane&15;
      int b = w2*2 + hw;
      float v = sc[b][l4];
      unsigned u = __float_as_uint(v);
      u = (u & 0x80000000u) ? ~u : (u | 0x80000000u);
      ull key = ((ull)u << 32) | (unsigned)(MM - (m0 + l4));
      #pragma unroll
      for (int k2=2; k2<=16; k2<<=1){
        #pragma unroll
        for (int j=k2>>1; j>0; j>>=1){
          ull o = __shfl_xor_sync(0xffffffffu, key, j);
          bool keep_max = ((l4 & k2)==0) == ((l4 & j)==0);
          key = keep_max ? (key > o ? key : o) : (key < o ? key : o);
        }
      }
      if (l4 < 8) __stcg(&g_ck[(size_t)(blk*BB+b)*TK + l4], key);
    }
    __syncthreads();
    // base partials: 2 threads per d; r-paired fma.f32x2
    {
      int d = tid>>1, half = tid&1;
      ull accp[8];
      #pragma unroll
      for (int z=0;z<8;z++) accp[z]=0ull;
      #pragma unroll
      for (int rp=0; rp<8; rp++){
        ull rrp = pk2(rowsf[(2*rp)*256 + d], rowsf[(2*rp+1)*256 + d]);
        const ulonglong2* ee2 = (const ulonglong2*)(esm2 + rp*16 + half*8);
        ulonglong2 e01 = ee2[0], e23 = ee2[1], e45 = ee2[2], e67 = ee2[3];
        fma2(accp[0], e01.x, rrp); fma2(accp[1], e01.y, rrp);
        fma2(accp[2], e23.x, rrp); fma2(accp[3], e23.y, rrp);
        fma2(accp[4], e45.x, rrp); fma2(accp[5], e45.y, rrp);
        fma2(accp[6], e67.x, rrp); fma2(accp[7], e67.y, rrp);
      }
      float av[8];
      #pragma unroll
      for (int z=0;z<8;z++) av[z] = upk_sum(accp[z]);
      *(float4*)&sbuf[d*16 + half*8]     = make_float4(av[0],av[1],av[2],av[3]);
      *(float4*)&sbuf[d*16 + half*8 + 4] = make_float4(av[4],av[5],av[6],av[7]);
    }
    __syncthreads();
    // dirty partial corrections: warp w owns batch eb==w
    {
      float corr[8] = {0.f,0.f,0.f,0.f,0.f,0.f,0.f,0.f};
      bool any = false;
      for (int e=0;e<dn;e++){
        int pk = dlist[e];
        if ((pk>>16) == wid){
          int er = (pk>>12)&15, es = pk&0xfff;
          float ev = upk_sel(esm2[(er>>1)*16 + wid], er&1);
          const float* ov = g_ovl + ((size_t)wid*OV + es)*DD;
          any = true;
          #pragma unroll
          for (int k=0;k<8;k++){
            int d = lane+32*k;
            corr[k] = fmaf(ev, __ldcg(&ov[d]) - rowsf[er*256 + d], corr[k]);
          }
        }
      }
      if (any){
        #pragma unroll
        for (int k=0;k<8;k++){ int d = lane+32*k; sbuf[d*16 + wid] += corr[k]; }
      }
    }
    __syncthreads();
    // store partials [k][d][b]
    {
      int d = tid>>1, half = tid&1;
      float4* gp4 = (float4*)g_part;
      __stcg(&gp4[((size_t)blk*256 + d)*4 + half*2 + 0], *(const float4*)&sbuf[d*16 + half*8]);
      __stcg(&gp4[((size_t)blk*256 + d)*4 + half*2 + 1], *(const float4*)&sbuf[d*16 + half*8 + 4]);
    }
    gbar(++bid);

    // ================= Phase C1 =================
    // h reduce for this block's d-chunk (warp0 finish; 1 syncthreads)
    {
      const float4* gp4 = (const float4*)g_part;
      int q = tid&7, kg = tid>>3;
      float4 a4 = __ldcg(&gp4[((size_t)kg*256 + dd0 + (q>>2))*4 + (q&3)]);
      float4 b4 = __ldcg(&gp4[((size_t)(kg+64)*256 + dd0 + (q>>2))*4 + (q&3)]);
      a4.x += b4.x; a4.y += b4.y; a4.z += b4.z; a4.w += b4.w;
      #pragma unroll
      for (int off=8; off<=16; off<<=1){
        a4.x += __shfl_xor_sync(0xffffffffu, a4.x, off);
        a4.y += __shfl_xor_sync(0xffffffffu, a4.y, off);
        a4.z += __shfl_xor_sync(0xffffffffu, a4.z, off);
        a4.w += __shfl_xor_sync(0xffffffffu, a4.w, off);
      }
      if (lane < 8) hred4[wid*8 + lane] = a4;
      __syncthreads();
      if (wid == 0){
        float4 u0 = hred4[lane],    u1 = hred4[lane+32];
        float4 u2 = hred4[lane+64], u3 = hred4[lane+96];
        float4 a;
        a.x = (u0.x+u1.x)+(u2.x+u3.x);
        a.y = (u0.y+u1.y)+(u2.y+u3.y);
        a.z = (u0.z+u1.z)+(u2.z+u3.z);
        a.w = (u0.w+u1.w)+(u2.w+u3.w);
        #pragma unroll
        for (int off=8; off<=16; off<<=1){
          a.x += __shfl_xor_sync(0xffffffffu, a.x, off);
          a.y += __shfl_xor_sync(0xffffffffu, a.y, off);
          a.z += __shfl_xor_sync(0xffffffffu, a.z, off);
          a.w += __shfl_xor_sync(0xffffffffu, a.w, off);
        }
        if (lane < 8) __stcg(&((float4*)g_h)[dd0*4 + lane], a);
      }
    }
    // local 1/Z for all 16 batches
    {
      const float4* ps4 = (const float4*)&g_psum[wid*NB];
      float4 p4 = __ldcg(&ps4[lane]);
      float zp = (p4.x+p4.y)+(p4.z+p4.w);
      #pragma unroll
      for (int off=16; off; off>>=1) zp += __shfl_xor_sync(0xffffffffu, zp, off);
      if (lane==0) zin_s[wid] = 1.0f/zp;
    }
    if (t+1 < SS){
      const float4* q4 = (const float4*)(g_qk + (size_t)(t+1)*BB*DD);
      float4* qd = (float4*)qks;
      for (int i=tid;i<1024;i+=NT) qd[i] = __ldg(&q4[i]);
    }
    if (blk < BB && t < SS-1){
      int b2 = blk;
      // stage 1: 16 warps x 64 candidates -> per-warp top-8 (warp-local)
      {
        ull k0, k1;
        {
          int c0 = wid*64 + lane;
          int c1 = wid*64 + 32 + lane;
          k0 = __ldcg(&g_ck[(size_t)((c0>>3)*BB + b2)*TK + (c0&7)]);
          k1 = __ldcg(&g_ck[(size_t)((c1>>3)*BB + b2)*TK + (c1&7)]);
        }
        #pragma unroll
        for (int round=0; round<TK; round++){
          ull k = k0 > k1 ? k0 : k1;
          #pragma unroll
          for (int off=16; off; off>>=1){
            ull o = __shfl_xor_sync(0xffffffffu, k, off);
            if (o > k) k = o;
          }
          if (lane == round) wtop[wid*8 + round] = k;
          if (k0 == k) k0 = 0ull;
          if (k1 == k) k1 = 0ull;
        }
      }
      __syncthreads();
      // stage 2: warp 0 merges 128 keys (4/lane)
      if (wid == 0){
        ull kl[4];
        kl[0] = wtop[lane]; kl[1] = wtop[lane+32];
        kl[2] = wtop[lane+64]; kl[3] = wtop[lane+96];
        int myrow = 0;
        #pragma unroll
        for (int round=0; round<TK; round++){
          ull k = kl[0];
          if (kl[1] > k) k = kl[1];
          if (kl[2] > k) k = kl[2];
          if (kl[3] > k) k = kl[3];
          #pragma unroll
          for (int off=16; off; off>>=1){
            ull o = __shfl_xor_sync(0xffffffffu, k, off);
            if (o > k) k = o;
          }
          if (lane == round) myrow = MM - (int)(unsigned)(k & 0xFFFFFFFFu);
          #pragma unroll
          for (int z=0;z<4;z++) if (kl[z]==k) kl[z] = 0ull;
        }
        bool valid = lane < TK;
        int row = valid ? myrow : 0;
        int s = valid ? __ldcg(&g_slot[b2*MM + row]) : 0;
        unsigned nm = __ballot_sync(0xffffffffu, valid && s < 0);
        int cnt0 = 0;
        if (lane==0) cnt0 = __ldcg(&g_ovcnt[b2]);
        cnt0 = __shfl_sync(0xffffffffu, cnt0, 0);
        if (valid){
          int prev = s, slot = s;
          if (s < 0){
            slot = cnt0 + __popc(nm & ((1u<<lane)-1));
            __stcg(&g_slot[b2*MM + row], slot);
          }
          __stcg(&g_tk[b2*24 + lane*3 + 0], row);
          __stcg(&g_tk[b2*24 + lane*3 + 1], prev);
          __stcg(&g_tk[b2*24 + lane*3 + 2], slot);
        }
        if (lane==0) __stcg(&g_ovcnt[b2], cnt0 + __popc(nm));
      }
    }
    gbar(++bid);

    // ================= Phase C2 =================
    {
      const float4* h4g = (const float4*)g_h;
      float4* s4 = (float4*)sbuf;
      for (int i=tid;i<1024;i+=NT) s4[i] = __ldcg(&h4g[i]);
      if (t < SS-1){
        for (int i=tid;i<BB*TK*3;i+=NT) tk_s[i] = __ldcg(&g_tk[i]);
      }
      __syncthreads();
      // GEMV over all 512 threads (j-paired f32x2)
      {
        int b = tid&15, jseg = tid>>4;
        ull a0p=0ull, a1p=0ull, a2p=0ull, a3p=0ull;
        #pragma unroll
        for (int jj=0;jj<4;jj++){
          int j = jseg*8 + jj*2;
          ull hvp = pk2(sbuf[j*16 + b], sbuf[j*16 + 16 + b]);
          fma2(a0p, *(const ull*)&wrow[j],       hvp);
          fma2(a1p, *(const ull*)&wrow[256 + j], hvp);
          fma2(a2p, *(const ull*)&wrow[512 + j], hvp);
          fma2(a3p, *(const ull*)&wrow[768 + j], hvp);
        }
        float a0 = upk_sum(a0p), a1 = upk_sum(a1p);
        float a2 = upk_sum(a2p), a3 = upk_sum(a3p);
        a0 += __shfl_xor_sync(0xffffffffu, a0, 16);
        a1 += __shfl_xor_sync(0xffffffffu, a1, 16);
        a2 += __shfl_xor_sync(0xffffffffu, a2, 16);
        a3 += __shfl_xor_sync(0xffffffffu, a3, 16);
        if ((tid&16)==0){
          cacc[b][0][wid]=a0; cacc[b][1][wid]=a1; cacc[b][2][wid]=a2; cacc[b][3][wid]=a3;
        }
      }
      __syncthreads();
      if (tid < 64){
        int b = tid&15, o = tid>>4;
        float s = 0.f;
        #pragma unroll
        for (int w=0;w<16;w++) s += cacc[b][o][w];
        float zi = zin_s[b];
        if (o < 2){
          out[((size_t)b*SS+t)*DD + dd0 + o] = s*zi + sbv[o];
        } else {
          int di = o-2;
          float gg = s*zi + scv[di] + __ldg(&g_gx[((size_t)t*BB+b)*DD + dd0 + di]);
          sgate[b][di] = 1.0f/(1.0f+expf(-gg));
        }
      }
      __syncthreads();
      if (t < SS-1 && tid < 256){
        int ent = tid>>1, di = tid&1;
        int b = ent>>3, i = ent&7;
        int row  = tk_s[(b*TK+i)*3 + 0];
        int prev = tk_s[(b*TK+i)*3 + 1];
        int slot = tk_s[(b*TK+i)*3 + 2];
        int d = dd0 + di;
        float old = (prev < 0) ? __ldg(&base[(size_t)row*DD + d])
                               : __ldcg(&g_ovl[((size_t)b*OV + prev)*DD + d]);
        float g = sgate[b][di];
        float xd = __ldg(&x[((size_t)b*SS+t)*DD + d]);
        __stcg(&g_ovl[((size_t)b*OV + slot)*DD + d], old + g*(xd - old));
      }
    }
    gbar(++bid);
  }
}

// =================== launch ===================
extern "C" void kernel_launch(void* const* d_in, const int* in_sizes, int n_in,
                              void* d_out, int out_size){
  const float* x      = (const float*)d_in[0];
  const float* memory = (const float*)d_in[1];
  const float* Wq     = (const float*)d_in[2];
  const float* bq     = (const float*)d_in[3];
  const float* Wk     = (const float*)d_in[4];
  // bk contributes only a softmax-invariant constant -> dropped
  const float* Wv     = (const float*)d_in[6];
  const float* bv     = (const float*)d_in[7];
  const float* Wu     = (const float*)d_in[8];
  const float* bu     = (const float*)d_in[9];
  float* out = (float*)d_out;

  static int attr_done = 0;
  if (!attr_done){
    cudaFuncSetAttribute(persist, cudaFuncAttributeMaxDynamicSharedMemorySize, 49152);
    attr_done = 1;
  }

  p_init1<<<NB, 256>>>(Wq, bq, Wk, Wv, bv, Wu);
  p_init2<<<NB, 256>>>(x, bu);
  persist<<<NB, NT, 49152>>>(memory, x, Wv, bv, out);
}

// round 16
// speedup vs baseline: 1.6905x; 1.0008x over previous
#include <cuda_runtime.h>
#include <math.h>
#include <float.h>

#define BB 16
#define SS 64
#define MM 2048
#define DD 256
#define TK 8
#define OV 512
#define NB 128
#define NT 512
#define SCALE 0.0625f

typedef unsigned long long ull;

// ---- persistent state (no runtime allocs) ----
__device__ float g_ovl[BB*OV*DD];
__device__ int   g_slot[BB*MM];
__device__ int   g_ovcnt[BB];
__device__ __align__(16) float g_qk[SS*BB*DD];
__device__ __align__(16) float g_gx[SS*BB*DD];
__device__ float g_AT[DD*DD];
__device__ float g_avec[DD];
__device__ float g_WuT1[DD*DD];
__device__ float g_W2[DD*DD];
__device__ float g_cvec[DD];
__device__ __align__(16) float g_psum[BB*NB];      // [b][k]
__device__ __align__(16) float g_part[NB*DD*BB];   // [k][d][b]
__device__ __align__(16) float g_h[DD*BB];         // [j][b]
__device__ __align__(16) ull   g_ck[NB*BB*TK];     // packed candidates
__device__ int   g_tk[BB*TK*3];
// monotonic barrier state (zero at module load, advances every launch)
__device__ int   g_flag[NB*32];
__device__ int   g_gen2;

// =================== flag-array grid barrier (coordinator = block NB-1) ===================
__device__ __forceinline__ void gbar(int target){
  __syncthreads();
  int tid = threadIdx.x, blk = blockIdx.x;
  if (blk == NB-1){
    if (tid < NB-1){
      int v;
      do {
        asm volatile("ld.acquire.gpu.global.s32 %0, [%1];"
                     : "=r"(v) : "l"(&g_flag[tid*32]) : "memory");
      } while (v < target);
    }
    __syncthreads();
    if (tid == 0)
      asm volatile("st.release.gpu.global.s32 [%0], %1;"
                   :: "l"(&g_gen2), "r"(target) : "memory");
  } else {
    if (tid == 0){
      asm volatile("st.release.gpu.global.s32 [%0], %1;"
                   :: "l"(&g_flag[blk*32]), "r"(target) : "memory");
      int v;
      do {
        asm volatile("ld.acquire.gpu.global.s32 %0, [%1];"
                     : "=r"(v) : "l"(&g_gen2) : "memory");
      } while (v < target);
    }
    __syncthreads();
  }
}

// ---- packed f32x2 helpers ----
__device__ __forceinline__ void fma2(ull &d, ull a, ull b){
  asm("fma.rn.f32x2 %0, %1, %2, %0;" : "+l"(d) : "l"(a), "l"(b));
}
__device__ __forceinline__ ull pk2(float lo, float hi){
  ull r; asm("mov.b64 %0, {%1, %2};" : "=l"(r) : "f"(lo), "f"(hi)); return r;
}
__device__ __forceinline__ float upk_sum(ull v){
  float lo, hi; asm("mov.b64 {%0, %1}, %2;" : "=f"(lo), "=f"(hi) : "l"(v));
  return lo + hi;
}
__device__ __forceinline__ float upk_sel(ull v, int hi_sel){
  float lo, hi; asm("mov.b64 {%0, %1}, %2;" : "=f"(lo), "=f"(hi) : "l"(v));
  return hi_sel ? hi : lo;
}

// =================== the single kernel (512 threads) ===================
__global__ void __launch_bounds__(NT, 1)
persist(const float* __restrict__ x, const float* __restrict__ base,
        const float* __restrict__ Wq, const float* __restrict__ bq,
        const float* __restrict__ Wk, const float* __restrict__ Wv,
        const float* __restrict__ bv, const float* __restrict__ Wu,
        const float* __restrict__ bu, float* __restrict__ out){
  extern __shared__ float dsm[];
  float* rowsf = dsm;          // [16][256]
  float* qks   = dsm + 4096;   // [16][256]
  float* sbuf  = dsm + 8192;   // AB: spart[d][b] ; C2: h[j][b]

  __shared__ float sc[16][17];
  __shared__ __align__(16) ull esm2[128];       // [rp][b] packed (e[2rp],e[2rp+1])
  __shared__ int   dlist[256];
  __shared__ int   dcnt_s;
  __shared__ __align__(16) ull wtop[128];
  __shared__ __align__(16) float4 hred4[128];
  __shared__ __align__(16) float wrow[4*DD];
  __shared__ float cacc[16][4][17];
  __shared__ float sgate[16][2];
  __shared__ int   tk_s[BB*TK*3];
  __shared__ float zin_s[16];
  __shared__ float sbv[2], scv[2];

  int blk = blockIdx.x, tid = threadIdx.x;
  int m0 = blk*16;
  int wid = tid>>5, lane = tid&31;
  int dd0 = blk*2;

  // barrier generation base (stable: no block advances until all arrive)
  int T0;
  asm volatile("ld.acquire.gpu.global.s32 %0, [%1];" : "=r"(T0) : "l"(&g_gen2) : "memory");

  // ================= init stage 1 =================
  if (blk < 32){                       // WuT1[j][d] = Wu[d][j]
    int base0 = blk*2048;
    #pragma unroll
    for (int z=0;z<4;z++){ int e = base0 + z*512 + tid; int d = e>>8, j = e&255;
      g_WuT1[j*DD+d] = Wu[(size_t)d*2*DD + j]; }
  } else if (blk < 48){                // A tiles: g_AT[j][d]
    float (*aq)[68] = (float(*)[68])dsm;
    float (*ak)[68] = (float(*)[68])(dsm + 16*68);
    int tn = blk-32, j0 = (tn>>2)*64, d0 = (tn&3)*64;
    int ty = (tid&255)>>4, tx = tid&15;
    float acc[16];
    #pragma unroll
    for (int z=0;z<16;z++) acc[z]=0.f;
    for (int ib=0; ib<DD; ib+=16){
      #pragma unroll
      for (int z=0;z<2;z++){ int e = z*512+tid; int i=e>>6, j=e&63;
        aq[i][j] = Wq[(size_t)(ib+i)*DD + j0 + j];
        ak[i][j] = Wk[(size_t)(ib+i)*DD + d0 + j]; }
      __syncthreads();
      if (tid < 256){
        #pragma unroll
        for (int i=0;i<16;i++){
          float qv[4], kv[4];
          #pragma unroll
          for (int u=0;u<4;u++){ qv[u]=aq[i][ty*4+u]; kv[u]=ak[i][tx*4+u]; }
          #pragma unroll
          for (int jr=0;jr<4;jr++)
            #pragma unroll
            for (int dr=0;dr<4;dr++) acc[jr*4+dr] = fmaf(qv[jr], kv[dr], acc[jr*4+dr]);
        }
      }
      __syncthreads();
    }
    if (tid < 256){
      #pragma unroll
      for (int jr=0;jr<4;jr++)
        #pragma unroll
        for (int dr=0;dr<4;dr++)
          g_AT[(size_t)(j0+ty*4+jr)*DD + d0+tx*4+dr] = acc[jr*4+dr]*SCALE;
    }
  } else if (blk < 64){                // W2 tiles [d][i]
    float (*wv)[68] = (float(*)[68])dsm;
    float (*wu)[68] = (float(*)[68])(dsm + 16*68);
    int tn = blk-48, i0 = (tn>>2)*64, d0 = (tn&3)*64;
    int ty = (tid&255)>>4, tx = tid&15;
    float acc[16];
    #pragma unroll
    for (int z=0;z<16;z++) acc[z]=0.f;
    for (int jb=0; jb<DD; jb+=16){
      #pragma unroll
      for (int z=0;z<2;z++){ int e = z*512+tid; int jj=e>>6, ii=e&63;
        wv[jj][ii] = Wv[(size_t)(jb+jj)*DD + i0 + ii];
        wu[jj][ii] = Wu[(size_t)(d0+ii)*2*DD + DD + jb + jj]; }
      __syncthreads();
      if (tid < 256){
        #pragma unroll
        for (int jj=0;jj<16;jj++){
          float vv[4], uv[4];
          #pragma unroll
          for (int u=0;u<4;u++){ vv[u]=wv[jj][ty*4+u]; uv[u]=wu[jj][tx*4+u]; }
          #pragma unroll
          for (int ir=0;ir<4;ir++)
            #pragma unroll
            for (int dr=0;dr<4;dr++) acc[ir*4+dr] = fmaf(vv[ir], uv[dr], acc[ir*4+dr]);
        }
      }
      __syncthreads();
    }
    if (tid < 256){
      #pragma unroll
      for (int ir=0;ir<4;ir++)
        #pragma unroll
        for (int dr=0;dr<4;dr++)
          g_W2[(size_t)(d0+tx*4+dr)*DD + i0+ty*4+ir] = acc[ir*4+dr];
    }
  } else if (blk < 80){                // slot map clear
    int base0 = (blk-64)*2048;
    #pragma unroll
    for (int z=0;z<4;z++) g_slot[base0 + z*512 + tid] = -1;
  } else if (blk == 80){
    if (tid < BB) g_ovcnt[tid] = 0;
  } else if (blk == 81){               // avec
    __shared__ float bqs[DD];
    if (tid < 256) bqs[tid] = bq[tid];
    __syncthreads();
    if (tid < 256){
      float acc = 0.f;
      #pragma unroll 4
      for (int i=0;i<DD;i++) acc = fmaf(Wk[(size_t)i*DD+tid], bqs[i], acc);
      g_avec[tid] = acc*SCALE;
    }
  } else if (blk == 82){               // cvec
    __shared__ float bvs[DD];
    if (tid < 256) bvs[tid] = bv[tid];
    __syncthreads();
    if (tid < 256){
      float acc = 0.f;
      #pragma unroll 4
      for (int j=0;j<DD;j++) acc = fmaf(Wu[(size_t)tid*2*DD + DD + j], bvs[j], acc);
      g_cvec[tid] = acc;
    }
  }
  gbar(T0+1);

  // ================= init stage 2: qk / gx GEMMs =================
  {
    float (*xt)[17] = (float(*)[17])dsm;
    float (*wt)[68] = (float(*)[68])(dsm + 64*17);
    int which = blk>>6;
    int r = blk&63;
    int s0 = (r>>2)*64, d0 = (r&3)*64;
    const float* W = which ? g_WuT1 : g_AT;
    int ty = (tid&255)>>4, tx = tid&15;
    float acc[16];
    #pragma unroll
    for (int z=0;z<16;z++) acc[z]=0.f;
    for (int jb=0; jb<DD; jb+=16){
      if (tid < 256){
        int ss = tid>>2, jq = tid&3;
        float4 xv = *(const float4*)&x[(size_t)(s0+ss)*DD + jb + jq*4];
        xt[ss][jq*4+0]=xv.x; xt[ss][jq*4+1]=xv.y; xt[ss][jq*4+2]=xv.z; xt[ss][jq*4+3]=xv.w;
      }
      #pragma unroll
      for (int z=0;z<2;z++){ int e = z*512+tid; int jj=e>>6, dd=e&63;
        wt[jj][dd] = W[(size_t)(jb+jj)*DD + d0 + dd]; }
      __syncthreads();
      if (tid < 256){
        #pragma unroll
        for (int jj=0;jj<16;jj++){
          float xv[4], wv4[4];
          #pragma unroll
          for (int u=0;u<4;u++){ xv[u]=xt[ty*4+u][jj]; wv4[u]=wt[jj][tx*4+u]; }
          #pragma unroll
          for (int sr=0;sr<4;sr++)
            #pragma unroll
            for (int dr=0;dr<4;dr++) acc[sr*4+dr] = fmaf(xv[sr], wv4[dr], acc[sr*4+dr]);
        }
      }
      __syncthreads();
    }
    if (tid < 256){
      float* dst = which ? g_gx : g_qk;
      const float* bias = which ? bu : g_avec;
      #pragma unroll
      for (int sr=0;sr<4;sr++){
        int s = s0 + ty*4 + sr;
        int b = s>>6, t = s&63;
        size_t ro = (size_t)(t*BB+b)*DD + d0 + tx*4;
        #pragma unroll
        for (int dr=0;dr<4;dr++) dst[ro+dr] = acc[sr*4+dr] + bias[d0+tx*4+dr];
      }
    }
  }
  gbar(T0+2);

  // ================= persistent smem loads =================
  for (int i=tid;i<16*DD;i+=NT) rowsf[i] = base[(size_t)m0*DD + i];
  {
    const float4* q4 = (const float4*)g_qk;
    float4* qd = (float4*)qks;
    for (int i=tid;i<1024;i+=NT) qd[i] = __ldcg(&q4[i]);
  }
  { int i = tid; if (i < 2*DD){ wrow[i] = Wv[(size_t)dd0*DD + i]; wrow[2*DD+i] = g_W2[(size_t)dd0*DD + i]; } }
  if (tid<2){ sbv[tid] = bv[dd0+tid]; scv[tid] = g_cvec[dd0+tid]; }
  __syncthreads();

  // ---- loop-invariant register cache: score GEMM base rows ----
  int sg_bq0 = (wid&3)*4, sg_r0 = (wid>>2)*4, sg_j0 = lane*8;
  float4 ra_c[8];
  #pragma unroll
  for (int hh=0; hh<2; hh++)
    #pragma unroll
    for (int u=0;u<4;u++)
      ra_c[hh*4+u] = *(const float4*)&rowsf[(sg_r0+u)*256 + sg_j0 + hh*4];

  int bid = T0+2;
  for (int t=0;t<SS;t++){
    // ================= Phase AB =================
    if (tid==0) dcnt_s = 0;
    __syncthreads();
    if (tid < 256){
      int b = tid>>4, r = tid&15;
      int s = __ldcg(&g_slot[b*MM + m0 + r]);
      if (s >= 0){ int p = atomicAdd(&dcnt_s,1); dlist[p] = (b<<16)|(r<<12)|s; }
    }
    // score GEMM: 4x4 tile/warp, lane splits K; j-paired fma.f32x2
    {
      ull acc2[16];
      #pragma unroll
      for (int z=0;z<16;z++) acc2[z]=0ull;
      #pragma unroll
      for (int hh=0; hh<2; hh++){
        int jb = sg_j0 + hh*4;
        ulonglong2 qa2[4];
        #pragma unroll
        for (int u=0;u<4;u++) qa2[u] = *(const ulonglong2*)&qks[(sg_bq0+u)*256 + jb];
        #pragma unroll
        for (int bi=0;bi<4;bi++)
          #pragma unroll
          for (int ri=0;ri<4;ri++){
            ulonglong2 rr = *(const ulonglong2*)&ra_c[hh*4+ri];
            fma2(acc2[bi*4+ri], qa2[bi].x, rr.x);
            fma2(acc2[bi*4+ri], qa2[bi].y, rr.y);
          }
      }
      float acc[16];
      #pragma unroll
      for (int z=0;z<16;z++) acc[z] = upk_sum(acc2[z]);
      {
        bool hi = (lane & 16);
        #pragma unroll
        for (int z=0;z<8;z++){
          float send = hi ? acc[z] : acc[z+8];
          float r = __shfl_xor_sync(0xffffffffu, send, 16);
          acc[z] = (hi ? acc[z+8] : acc[z]) + r;
        }
      }
      {
        bool hi = (lane & 8);
        #pragma unroll
        for (int z=0;z<4;z++){
          float send = hi ? acc[z] : acc[z+4];
          float r = __shfl_xor_sync(0xffffffffu, send, 8);
          acc[z] = (hi ? acc[z+4] : acc[z]) + r;
        }
      }
      {
        bool hi = (lane & 4);
        #pragma unroll
        for (int z=0;z<2;z++){
          float send = hi ? acc[z] : acc[z+2];
          float r = __shfl_xor_sync(0xffffffffu, send, 4);
          acc[z] = (hi ? acc[z+2] : acc[z]) + r;
        }
      }
      {
        bool hi = (lane & 2);
        float send = hi ? acc[0] : acc[1];
        float r = __shfl_xor_sync(0xffffffffu, send, 2);
        acc[0] = (hi ? acc[1] : acc[0]) + r;
      }
      acc[0] += __shfl_xor_sync(0xffffffffu, acc[0], 1);
      if ((lane & 1) == 0){
        int z = (lane>>1) & 15;
        sc[sg_bq0 + (z>>2)][sg_r0 + (z&3)] = acc[0];
      }
    }
    __syncthreads();
    int dn = dcnt_s;
    // dirty score fixes (16 warps over entries)
    for (int e=wid; e<dn; e+=16){
      int pk = dlist[e]; int eb = pk>>16, er = (pk>>12)&15, es = pk&0xfff;
      const float* ov = g_ovl + ((size_t)eb*OV + es)*DD;
      float a2 = 0.f;
      #pragma unroll
      for (int k=0;k<8;k++) a2 = fmaf(__ldcg(&ov[lane+32*k]), qks[eb*256 + lane+32*k], a2);
      #pragma unroll
      for (int off=16; off; off>>=1) a2 += __shfl_xor_sync(0xffffffffu, a2, off);
      if (lane==0) sc[eb][er] = a2;
    }
    __syncthreads();
    // exp + psum + packed-pair store (warps 0-7) ; candidate bitonic top-8 (warps 8-15)
    if (tid < 256){
      int b = tid>>4, r = tid&15;
      float e = expf(sc[b][r]);
      float eo = __shfl_down_sync(0xffffffffu, e, 1);
      if ((r & 1) == 0) esm2[(r>>1)*16 + b] = pk2(e, eo);
      float ps = e;
      #pragma unroll
      for (int off=8; off; off>>=1) ps += __shfl_xor_sync(0xffffffffu, ps, off);
      if (r==0) __stcg(&g_psum[b*NB + blk], ps);
    } else if (t < SS-1){
      int w2 = wid - 8;
      int hw = lane>>4, l4 = lane&15;
      int b = w2*2 + hw;
      float v = sc[b][l4];
      unsigned u = __float_as_uint(v);
      u = (u & 0x80000000u) ? ~u : (u | 0x80000000u);
      ull key = ((ull)u << 32) | (unsigned)(MM - (m0 + l4));
      #pragma unroll
      for (int k2=2; k2<=16; k2<<=1){
        #pragma unroll
        for (int j=k2>>1; j>0; j>>=1){
          ull o = __shfl_xor_sync(0xffffffffu, key, j);
          bool keep_max = ((l4 & k2)==0) == ((l4 & j)==0);
          key = keep_max ? (key > o ? key : o) : (key < o ? key : o);
        }
      }
      if (l4 < 8) __stcg(&g_ck[(size_t)(blk*BB+b)*TK + l4], key);
    }
    __syncthreads();
    // base partials: 2 threads per d; r-paired fma.f32x2
    {
      int d = tid>>1, half = tid&1;
      ull accp[8];
      #pragma unroll
      for (int z=0;z<8;z++) accp[z]=0ull;
      #pragma unroll
      for (int rp=0; rp<8; rp++){
        ull rrp = pk2(rowsf[(2*rp)*256 + d], rowsf[(2*rp+1)*256 + d]);
        const ulonglong2* ee2 = (const ulonglong2*)(esm2 + rp*16 + half*8);
        ulonglong2 e01 = ee2[0], e23 = ee2[1], e45 = ee2[2], e67 = ee2[3];
        fma2(accp[0], e01.x, rrp); fma2(accp[1], e01.y, rrp);
        fma2(accp[2], e23.x, rrp); fma2(accp[3], e23.y, rrp);
        fma2(accp[4], e45.x, rrp); fma2(accp[5], e45.y, rrp);
        fma2(accp[6], e67.x, rrp); fma2(accp[7], e67.y, rrp);
      }
      float av[8];
      #pragma unroll
      for (int z=0;z<8;z++) av[z] = upk_sum(accp[z]);
      *(float4*)&sbuf[d*16 + half*8]     = make_float4(av[0],av[1],av[2],av[3]);
      *(float4*)&sbuf[d*16 + half*8 + 4] = make_float4(av[4],av[5],av[6],av[7]);
    }
    __syncthreads();
    // dirty partial corrections: warp w owns batch eb==w
    {
      float corr[8] = {0.f,0.f,0.f,0.f,0.f,0.f,0.f,0.f};
      bool any = false;
      for (int e=0;e<dn;e++){
        int pk = dlist[e];
        if ((pk>>16) == wid){
          int er = (pk>>12)&15, es = pk&0xfff;
          float ev = upk_sel(esm2[(er>>1)*16 + wid], er&1);
          const float* ov = g_ovl + ((size_t)wid*OV + es)*DD;
          any = true;
          #pragma unroll
          for (int k=0;k<8;k++){
            int d = lane+32*k;
            corr[k] = fmaf(ev, __ldcg(&ov[d]) - rowsf[er*256 + d], corr[k]);
          }
        }
      }
      if (any){
        #pragma unroll
        for (int k=0;k<8;k++){ int d = lane+32*k; sbuf[d*16 + wid] += corr[k]; }
      }
    }
    __syncthreads();
    // store partials [k][d][b]
    {
      int d = tid>>1, half = tid&1;
      float4* gp4 = (float4*)g_part;
      __stcg(&gp4[((size_t)blk*256 + d)*4 + half*2 + 0], *(const float4*)&sbuf[d*16 + half*8]);
      __stcg(&gp4[((size_t)blk*256 + d)*4 + half*2 + 1], *(const float4*)&sbuf[d*16 + half*8 + 4]);
    }
    gbar(++bid);

    // ================= Phase C1 =================
    // h reduce for this block's d-chunk (warp0 finish; 1 syncthreads)
    {
      const float4* gp4 = (const float4*)g_part;
      int q = tid&7, kg = tid>>3;
      float4 a4 = __ldcg(&gp4[((size_t)kg*256 + dd0 + (q>>2))*4 + (q&3)]);
      float4 b4 = __ldcg(&gp4[((size_t)(kg+64)*256 + dd0 + (q>>2))*4 + (q&3)]);
      a4.x += b4.x; a4.y += b4.y; a4.z += b4.z; a4.w += b4.w;
      #pragma unroll
      for (int off=8; off<=16; off<<=1){
        a4.x += __shfl_xor_sync(0xffffffffu, a4.x, off);
        a4.y += __shfl_xor_sync(0xffffffffu, a4.y, off);
        a4.z += __shfl_xor_sync(0xffffffffu, a4.z, off);
        a4.w += __shfl_xor_sync(0xffffffffu, a4.w, off);
      }
      if (lane < 8) hred4[wid*8 + lane] = a4;
      __syncthreads();
      if (wid == 0){
        float4 u0 = hred4[lane],    u1 = hred4[lane+32];
        float4 u2 = hred4[lane+64], u3 = hred4[lane+96];
        float4 a;
        a.x = (u0.x+u1.x)+(u2.x+u3.x);
        a.y = (u0.y+u1.y)+(u2.y+u3.y);
        a.z = (u0.z+u1.z)+(u2.z+u3.z);
        a.w = (u0.w+u1.w)+(u2.w+u3.w);
        #pragma unroll
        for (int off=8; off<=16; off<<=1){
          a.x += __shfl_xor_sync(0xffffffffu, a.x, off);
          a.y += __shfl_xor_sync(0xffffffffu, a.y, off);
          a.z += __shfl_xor_sync(0xffffffffu, a.z, off);
          a.w += __shfl_xor_sync(0xffffffffu, a.w, off);
        }
        if (lane < 8) __stcg(&((float4*)g_h)[dd0*4 + lane], a);
      }
    }
    // local 1/Z for all 16 batches
    {
      const float4* ps4 = (const float4*)&g_psum[wid*NB];
      float4 p4 = __ldcg(&ps4[lane]);
      float zp = (p4.x+p4.y)+(p4.z+p4.w);
      #pragma unroll
      for (int off=16; off; off>>=1) zp += __shfl_xor_sync(0xffffffffu, zp, off);
      if (lane==0) zin_s[wid] = 1.0f/zp;
    }
    if (t+1 < SS){
      const float4* q4 = (const float4*)(g_qk + (size_t)(t+1)*BB*DD);
      float4* qd = (float4*)qks;
      for (int i=tid;i<1024;i+=NT) qd[i] = __ldcg(&q4[i]);
    }
    if (blk < BB && t < SS-1){
      int b2 = blk;
      // stage 1: 16 warps x 64 candidates -> per-warp top-8 (warp-local)
      {
        ull k0, k1;
        {
          int c0 = wid*64 + lane;
          int c1 = wid*64 + 32 + lane;
          k0 = __ldcg(&g_ck[(size_t)((c0>>3)*BB + b2)*TK + (c0&7)]);
          k1 = __ldcg(&g_ck[(size_t)((c1>>3)*BB + b2)*TK + (c1&7)]);
        }
        #pragma unroll
        for (int round=0; round<TK; round++){
          ull k = k0 > k1 ? k0 : k1;
          #pragma unroll
          for (int off=16; off; off>>=1){
            ull o = __shfl_xor_sync(0xffffffffu, k, off);
            if (o > k) k = o;
          }
          if (lane == round) wtop[wid*8 + round] = k;
          if (k0 == k) k0 = 0ull;
          if (k1 == k) k1 = 0ull;
        }
      }
      __syncthreads();
      // stage 2: warp 0 merges 128 keys (4/lane)
      if (wid == 0){
        ull kl[4];
        kl[0] = wtop[lane]; kl[1] = wtop[lane+32];
        kl[2] = wtop[lane+64]; kl[3] = wtop[lane+96];
        int myrow = 0;
        #pragma unroll
        for (int round=0; round<TK; round++){
          ull k = kl[0];
          if (kl[1] > k) k = kl[1];
          if (kl[2] > k) k = kl[2];
          if (kl[3] > k) k = kl[3];
          #pragma unroll
          for (int off=16; off; off>>=1){
            ull o = __shfl_xor_sync(0xffffffffu, k, off);
            if (o > k) k = o;
          }
          if (lane == round) myrow = MM - (int)(unsigned)(k & 0xFFFFFFFFu);
          #pragma unroll
          for (int z=0;z<4;z++) if (kl[z]==k) kl[z] = 0ull;
        }
        bool valid = lane < TK;
        int row = valid ? myrow : 0;
        int s = valid ? __ldcg(&g_slot[b2*MM + row]) : 0;
        unsigned nm = __ballot_sync(0xffffffffu, valid && s < 0);
        int cnt0 = 0;
        if (lane==0) cnt0 = __ldcg(&g_ovcnt[b2]);
        cnt0 = __shfl_sync(0xffffffffu, cnt0, 0);
        if (valid){
          int prev = s, slot = s;
          if (s < 0){
            slot = cnt0 + __popc(nm & ((1u<<lane)-1));
            __stcg(&g_slot[b2*MM + row], slot);
          }
          __stcg(&g_tk[b2*24 + lane*3 + 0], row);
          __stcg(&g_tk[b2*24 + lane*3 + 1], prev);
          __stcg(&g_tk[b2*24 + lane*3 + 2], slot);
        }
        if (lane==0) __stcg(&g_ovcnt[b2], cnt0 + __popc(nm));
      }
    }
    gbar(++bid);

    // ================= Phase C2 =================
    {
      const float4* h4g = (const float4*)g_h;
      float4* s4 = (float4*)sbuf;
      for (int i=tid;i<1024;i+=NT) s4[i] = __ldcg(&h4g[i]);
      if (t < SS-1){
        for (int i=tid;i<BB*TK*3;i+=NT) tk_s[i] = __ldcg(&g_tk[i]);
      }
      __syncthreads();
      // GEMV over all 512 threads (j-paired f32x2)
      {
        int b = tid&15, jseg = tid>>4;
        ull a0p=0ull, a1p=0ull, a2p=0ull, a3p=0ull;
        #pragma unroll
        for (int jj=0;jj<4;jj++){
          int j = jseg*8 + jj*2;
          ull hvp = pk2(sbuf[j*16 + b], sbuf[j*16 + 16 + b]);
          fma2(a0p, *(const ull*)&wrow[j],       hvp);
          fma2(a1p, *(const ull*)&wrow[256 + j], hvp);
          fma2(a2p, *(const ull*)&wrow[512 + j], hvp);
          fma2(a3p, *(const ull*)&wrow[768 + j], hvp);
        }
        float a0 = upk_sum(a0p), a1 = upk_sum(a1p);
        float a2 = upk_sum(a2p), a3 = upk_sum(a3p);
        a0 += __shfl_xor_sync(0xffffffffu, a0, 16);
        a1 += __shfl_xor_sync(0xffffffffu, a1, 16);
        a2 += __shfl_xor_sync(0xffffffffu, a2, 16);
        a3 += __shfl_xor_sync(0xffffffffu, a3, 16);
        if ((tid&16)==0){
          cacc[b][0][wid]=a0; cacc[b][1][wid]=a1; cacc[b][2][wid]=a2; cacc[b][3][wid]=a3;
        }
      }
      __syncthreads();
      if (tid < 64){
        int b = tid&15, o = tid>>4;
        float s = 0.f;
        #pragma unroll
        for (int w=0;w<16;w++) s += cacc[b][o][w];
        float zi = zin_s[b];
        if (o < 2){
          out[((size_t)b*SS+t)*DD + dd0 + o] = s*zi + sbv[o];
        } else {
          int di = o-2;
          float gg = s*zi + scv[di] + __ldg(&g_gx[((size_t)t*BB+b)*DD + dd0 + di]);
          sgate[b][di] = 1.0f/(1.0f+expf(-gg));
        }
      }
      __syncthreads();
      if (t < SS-1 && tid < 256){
        int ent = tid>>1, di = tid&1;
        int b = ent>>3, i = ent&7;
        int row  = tk_s[(b*TK+i)*3 + 0];
        int prev = tk_s[(b*TK+i)*3 + 1];
        int slot = tk_s[(b*TK+i)*3 + 2];
        int d = dd0 + di;
        float old = (prev < 0) ? __ldg(&base[(size_t)row*DD + d])
                               : __ldcg(&g_ovl[((size_t)b*OV + prev)*DD + d]);
        float g = sgate[b][di];
        float xd = __ldg(&x[((size_t)b*SS+t)*DD + d]);
        __stcg(&g_ovl[((size_t)b*OV + slot)*DD + d], old + g*(xd - old));
      }
    }
    gbar(++bid);
  }
}

// =================== launch: single kernel ===================
extern "C" void kernel_launch(void* const* d_in, const int* in_sizes, int n_in,
                              void* d_out, int out_size){
  const float* x      = (const float*)d_in[0];
  const float* memory = (const float*)d_in[1];
  const float* Wq     = (const float*)d_in[2];
  const float* bq     = (const float*)d_in[3];
  const float* Wk     = (const float*)d_in[4];
  // bk contributes only a softmax-invariant constant -> dropped
  const float* Wv     = (const float*)d_in[6];
  const float* bv     = (const float*)d_in[7];
  const float* Wu     = (const float*)d_in[8];
  const float* bu     = (const float*)d_in[9];
  float* out = (float*)d_out;

  static int attr_done = 0;
  if (!attr_done){
    cudaFuncSetAttribute(persist, cudaFuncAttributeMaxDynamicSharedMemorySize, 49152);
    attr_done = 1;
  }

  persist<<<NB, NT, 49152>>>(x, memory, Wq, bq, Wk, Wv, bv, Wu, bu, out);
}